// round 1
// baseline (speedup 1.0000x reference)
#include <cuda_runtime.h>

// ---------------------------------------------------------------------------
// AtomAttentionEncoder fused pipeline (fp32 baseline, round 1)
// B=2, N=16384, CA=CS=128, CZ=16, H=4, NQ=32, NK=128, DH=32, NB=512
// ---------------------------------------------------------------------------

constexpr int B_  = 2;
constexpr int N_  = 16384;
constexpr int CA_ = 128;
constexpr int CZ_ = 16;
constexpr int H_  = 4;
constexpr int NQ_ = 32;
constexpr int NK_ = 128;
constexpr int DH_ = 32;
constexpr int NB_ = 512;

constexpr int    M_   = B_ * N_;               // 32768 tokens
constexpr size_t SLOT = (size_t)M_ * CA_;      // 4,194,304 floats = 16 MB

// scratch: 21 slots of (M x 128) fp32
__device__ float g_scratch[21 * SLOT];

__device__ __forceinline__ float sigmoidf_(float x) { return 1.0f / (1.0f + __expf(-x)); }

// ---------------------------------------------------------------------------
// LayerNorm kernel: per token (warp) computes
//   a_n   = LN(a)
//   s_apb = LN(s) * apb_gamma_s
//   s_ct  = LN(s) * ct_gamma_s
// ---------------------------------------------------------------------------
__global__ void ln_kernel(const float* __restrict__ a, const float* __restrict__ s,
                          const float* __restrict__ apbg, const float* __restrict__ ctg,
                          float* __restrict__ a_n, float* __restrict__ s_apb,
                          float* __restrict__ s_ct)
{
    int warp = (blockIdx.x * blockDim.x + threadIdx.x) >> 5;
    int lane = threadIdx.x & 31;
    if (warp >= M_) return;
    size_t base = (size_t)warp * CA_;

    // ---- a ----
    float4 av = ((const float4*)(a + base))[lane];
    float sum = av.x + av.y + av.z + av.w;
    float sq  = av.x * av.x + av.y * av.y + av.z * av.z + av.w * av.w;
#pragma unroll
    for (int o = 16; o; o >>= 1) {
        sum += __shfl_xor_sync(0xffffffffu, sum, o);
        sq  += __shfl_xor_sync(0xffffffffu, sq,  o);
    }
    float m   = sum * (1.0f / 128.0f);
    float inv = rsqrtf(sq * (1.0f / 128.0f) - m * m + 1e-5f);
    float4 ao;
    ao.x = (av.x - m) * inv; ao.y = (av.y - m) * inv;
    ao.z = (av.z - m) * inv; ao.w = (av.w - m) * inv;
    ((float4*)(a_n + base))[lane] = ao;

    // ---- s ----
    float4 sv = ((const float4*)(s + base))[lane];
    float sums = sv.x + sv.y + sv.z + sv.w;
    float sqs  = sv.x * sv.x + sv.y * sv.y + sv.z * sv.z + sv.w * sv.w;
#pragma unroll
    for (int o = 16; o; o >>= 1) {
        sums += __shfl_xor_sync(0xffffffffu, sums, o);
        sqs  += __shfl_xor_sync(0xffffffffu, sqs,  o);
    }
    float ms   = sums * (1.0f / 128.0f);
    float invs = rsqrtf(sqs * (1.0f / 128.0f) - ms * ms + 1e-5f);
    float4 sn;
    sn.x = (sv.x - ms) * invs; sn.y = (sv.y - ms) * invs;
    sn.z = (sv.z - ms) * invs; sn.w = (sv.w - ms) * invs;

    float4 g1 = ((const float4*)apbg)[lane];
    float4 g2 = ((const float4*)ctg)[lane];
    float4 o1, o2;
    o1.x = sn.x * g1.x; o1.y = sn.y * g1.y; o1.z = sn.z * g1.z; o1.w = sn.w * g1.w;
    o2.x = sn.x * g2.x; o2.y = sn.y * g2.y; o2.z = sn.z * g2.z; o2.w = sn.w * g2.w;
    ((float4*)(s_apb + base))[lane] = o1;
    ((float4*)(s_ct  + base))[lane] = o2;
}

// ---------------------------------------------------------------------------
// SGEMM: C[M,N] = epilogue( A[M,K] (optionally * Apre elementwise) @ W[K,N] + bias )
// ep: 0 = none, 1 = sigmoid, 2 = C = e1*acc, 3 = C = e1*acc + e2
// Tiles: 128x128, KC=8, 256 threads, 8x8 per-thread microtile.
// ---------------------------------------------------------------------------
__global__ void __launch_bounds__(256) gemm_kernel(
    const float* __restrict__ A, const float* __restrict__ Apre,
    const float* __restrict__ W, const float* __restrict__ bias,
    float* __restrict__ C, int M, int N, int K,
    int ep, const float* __restrict__ e1, const float* __restrict__ e2)
{
    __shared__ float As[8][128];
    __shared__ float Bs[8][128];
    int tid = threadIdx.x;
    int tx = tid & 15, ty = tid >> 4;
    int row0 = blockIdx.x * 128;
    int col0 = blockIdx.y * 128;

    float acc[8][8];
#pragma unroll
    for (int i = 0; i < 8; i++)
#pragma unroll
        for (int j = 0; j < 8; j++) acc[i][j] = 0.0f;

    int am = tid >> 1;           // 0..127
    int ak = (tid & 1) * 4;      // 0 or 4
    int bk = tid >> 5;           // 0..7
    int bn = (tid & 31) * 4;     // 0..124

    for (int k0 = 0; k0 < K; k0 += 8) {
        float4 va = *(const float4*)(A + (size_t)(row0 + am) * K + k0 + ak);
        if (Apre) {
            float4 vp = *(const float4*)(Apre + (size_t)(row0 + am) * K + k0 + ak);
            va.x *= vp.x; va.y *= vp.y; va.z *= vp.z; va.w *= vp.w;
        }
        As[ak + 0][am] = va.x; As[ak + 1][am] = va.y;
        As[ak + 2][am] = va.z; As[ak + 3][am] = va.w;
        *(float4*)&Bs[bk][bn] = *(const float4*)(W + (size_t)(k0 + bk) * N + col0 + bn);
        __syncthreads();
#pragma unroll
        for (int kk = 0; kk < 8; kk++) {
            float af[8], bf[8];
            *(float4*)&af[0] = *(const float4*)&As[kk][ty * 8];
            *(float4*)&af[4] = *(const float4*)&As[kk][ty * 8 + 4];
            *(float4*)&bf[0] = *(const float4*)&Bs[kk][tx * 8];
            *(float4*)&bf[4] = *(const float4*)&Bs[kk][tx * 8 + 4];
#pragma unroll
            for (int i = 0; i < 8; i++)
#pragma unroll
                for (int j = 0; j < 8; j++)
                    acc[i][j] += af[i] * bf[j];
        }
        __syncthreads();
    }

    float bcol[8];
#pragma unroll
    for (int j = 0; j < 8; j++) bcol[j] = bias ? bias[col0 + tx * 8 + j] : 0.0f;

#pragma unroll
    for (int i = 0; i < 8; i++) {
        size_t r = (size_t)(row0 + ty * 8 + i);
#pragma unroll
        for (int j = 0; j < 8; j++) {
            size_t idx = r * N + col0 + tx * 8 + j;
            float v = acc[i][j] + bcol[j];
            if (ep == 1)      v = sigmoidf_(v);
            else if (ep == 2) v = e1[idx] * v;
            else if (ep == 3) v = e1[idx] * v + e2[idx];
            C[idx] = v;
        }
    }
}

// ---------------------------------------------------------------------------
// Combine: a1/a3 from the two adaLN branches, plus the two raw-s sigmoid gates.
// glast / sg are updated in place (raw GEMM out -> sigmoid(out + bias)).
// ---------------------------------------------------------------------------
__global__ void combine1_kernel(
    const float* __restrict__ gapb, const float* __restrict__ kapb,
    const float* __restrict__ gct,  const float* __restrict__ kct,
    float* __restrict__ glast, float* __restrict__ sg,
    const float* __restrict__ a_n,
    const float* __restrict__ bg, const float* __restrict__ ctbg,
    const float* __restrict__ bsl, const float* __restrict__ bsv,
    float* __restrict__ a1, float* __restrict__ a3)
{
    size_t i = (size_t)blockIdx.x * blockDim.x + threadIdx.x;  // float4 index
    int c = (int)(i & 31) * 4;
    float4 van = ((const float4*)a_n)[i];
    float4 v1, v2, o1;

    v1 = ((const float4*)gapb)[i];
    v2 = ((const float4*)kapb)[i];
    o1.x = sigmoidf_(v1.x + bg[c + 0]) * van.x + v2.x;
    o1.y = sigmoidf_(v1.y + bg[c + 1]) * van.y + v2.y;
    o1.z = sigmoidf_(v1.z + bg[c + 2]) * van.z + v2.z;
    o1.w = sigmoidf_(v1.w + bg[c + 3]) * van.w + v2.w;
    ((float4*)a1)[i] = o1;

    v1 = ((const float4*)gct)[i];
    v2 = ((const float4*)kct)[i];
    o1.x = sigmoidf_(v1.x + ctbg[c + 0]) * van.x + v2.x;
    o1.y = sigmoidf_(v1.y + ctbg[c + 1]) * van.y + v2.y;
    o1.z = sigmoidf_(v1.z + ctbg[c + 2]) * van.z + v2.z;
    o1.w = sigmoidf_(v1.w + ctbg[c + 3]) * van.w + v2.w;
    ((float4*)a3)[i] = o1;

    v1 = ((const float4*)glast)[i];
    o1.x = sigmoidf_(v1.x + bsl[c + 0]);
    o1.y = sigmoidf_(v1.y + bsl[c + 1]);
    o1.z = sigmoidf_(v1.z + bsl[c + 2]);
    o1.w = sigmoidf_(v1.w + bsl[c + 3]);
    ((float4*)glast)[i] = o1;

    v1 = ((const float4*)sg)[i];
    o1.x = sigmoidf_(v1.x + bsv[c + 0]);
    o1.y = sigmoidf_(v1.y + bsv[c + 1]);
    o1.z = sigmoidf_(v1.z + bsv[c + 2]);
    o1.w = sigmoidf_(v1.w + bsv[c + 3]);
    ((float4*)sg)[i] = o1;
}

// t = silu(u1) * u2, in place into u1 (M x 256)
__global__ void silu_kernel(float* __restrict__ u1, const float* __restrict__ u2)
{
    size_t i = (size_t)blockIdx.x * blockDim.x + threadIdx.x;  // float4 index
    float4 x = ((const float4*)u1)[i];
    float4 y = ((const float4*)u2)[i];
    float4 o;
    o.x = x.x * sigmoidf_(x.x) * y.x;
    o.y = x.y * sigmoidf_(x.y) * y.y;
    o.z = x.z * sigmoidf_(x.z) * y.z;
    o.w = x.w * sigmoidf_(x.w) * y.w;
    ((float4*)u1)[i] = o;
}

// ---------------------------------------------------------------------------
// Fused local attention. One CTA per (b, nb). Streams z once to build the
// 4-head bias in smem, then per-head K/V tiles (stride-33 padded), scores
// written in place over the bias slab, warp softmax, PV.
// ---------------------------------------------------------------------------
constexpr int ATTN_SMEM_FLOATS = H_ * NQ_ * NK_ + NQ_ * CA_ + 2 * NK_ * 33;  // 28928

__global__ void __launch_bounds__(256) attn_kernel(
    const float* __restrict__ q, const float* __restrict__ kg,
    const float* __restrict__ vg, const float* __restrict__ z,
    const float* __restrict__ gamma_z, const float* __restrict__ Wz,
    float* __restrict__ o)
{
    extern __shared__ float sm[];
    float* biasS = sm;                       // H*NQ*NK = 16384
    float* Qs = biasS + H_ * NQ_ * NK_;      // NQ*CA   = 4096
    float* Ks = Qs + NQ_ * CA_;              // NK*33   = 4224
    float* Vs = Ks + NK_ * 33;               // NK*33   = 4224
    __shared__ float gzs[CZ_];
    __shared__ float wzs[CZ_ * H_];

    int tid = threadIdx.x;
    int nb = blockIdx.x, b = blockIdx.y;
    if (tid < CZ_)      gzs[tid] = gamma_z[tid];
    if (tid < CZ_ * H_) wzs[tid] = Wz[tid];

    // Q tile: 32 tokens x 128 dims
    for (int e = tid; e < NQ_ * CA_ / 4; e += 256) {
        int qq = e >> 5;
        int c  = (e & 31) * 4;
        ((float4*)Qs)[e] = *(const float4*)(q + ((size_t)b * N_ + nb * NQ_ + qq) * CA_ + c);
    }
    __syncthreads();

    // bias: LN over CZ=16 then project to 4 heads; 4096 (q,k) pairs
    const float* zb = z + ((size_t)(b * NB_ + nb)) * NQ_ * NK_ * CZ_;
#pragma unroll 1
    for (int i = 0; i < 16; i++) {
        int p = tid + i * 256;
        const float4* zp = (const float4*)(zb + (size_t)p * CZ_);
        float4 z0 = zp[0], z1 = zp[1], z2 = zp[2], z3 = zp[3];
        float zv[16] = {z0.x, z0.y, z0.z, z0.w, z1.x, z1.y, z1.z, z1.w,
                        z2.x, z2.y, z2.z, z2.w, z3.x, z3.y, z3.z, z3.w};
        float mm = 0.0f;
#pragma unroll
        for (int c = 0; c < 16; c++) mm += zv[c];
        mm *= (1.0f / 16.0f);
        float ss2 = 0.0f;
#pragma unroll
        for (int c = 0; c < 16; c++) { float d = zv[c] - mm; ss2 += d * d; }
        float inv = rsqrtf(ss2 * (1.0f / 16.0f) + 1e-5f);
        float bh0 = 0, bh1 = 0, bh2 = 0, bh3 = 0;
#pragma unroll
        for (int c = 0; c < 16; c++) {
            float zn = (zv[c] - mm) * inv * gzs[c];
            bh0 += zn * wzs[c * 4 + 0];
            bh1 += zn * wzs[c * 4 + 1];
            bh2 += zn * wzs[c * 4 + 2];
            bh3 += zn * wzs[c * 4 + 3];
        }
        biasS[0 * 4096 + p] = bh0;
        biasS[1 * 4096 + p] = bh1;
        biasS[2 * 4096 + p] = bh2;
        biasS[3 * 4096 + p] = bh3;
    }
    __syncthreads();

    int kbase = nb * NQ_ - (NK_ - NQ_) / 2;  // - 48
    int warp = tid >> 5, lane = tid & 31;

    for (int h = 0; h < H_; h++) {
        // K/V tiles for this head: 128 keys x 32 dims, padded stride 33
        for (int e = tid; e < NK_ * DH_ / 4; e += 256) {
            int j = e >> 3;
            int d = (e & 7) * 4;
            int t = kbase + j;
            t = t < 0 ? 0 : (t >= N_ ? N_ - 1 : t);
            size_t off = ((size_t)b * N_ + t) * CA_ + h * DH_ + d;
            float4 kv = *(const float4*)(kg + off);
            Ks[j * 33 + d + 0] = kv.x; Ks[j * 33 + d + 1] = kv.y;
            Ks[j * 33 + d + 2] = kv.z; Ks[j * 33 + d + 3] = kv.w;
            float4 vv = *(const float4*)(vg + off);
            Vs[j * 33 + d + 0] = vv.x; Vs[j * 33 + d + 1] = vv.y;
            Vs[j * 33 + d + 2] = vv.z; Vs[j * 33 + d + 3] = vv.w;
        }
        __syncthreads();

        float* sc = biasS + h * (NQ_ * NK_);
#pragma unroll 1
        for (int i = 0; i < 16; i++) {
            int p = tid + i * 256;
            int qq = p >> 7, kj = p & 127;
            const float* qrow = Qs + qq * CA_ + h * DH_;
            const float* krow = Ks + kj * 33;
            float acc = 0.0f;
#pragma unroll
            for (int d = 0; d < 32; d++) acc += qrow[d] * krow[d];
            int t = kbase + kj;
            float svv = (t >= 0 && t < N_) ? acc * 0.17677669529663687f + sc[p]
                                           : -1e9f;
            sc[p] = svv;
        }
        __syncthreads();

        // softmax: each warp handles 4 query rows
#pragma unroll
        for (int rr = 0; rr < 4; rr++) {
            int r = warp * 4 + rr;
            float* row = sc + r * NK_;
            float v0 = row[lane], v1 = row[lane + 32], v2 = row[lane + 64], v3 = row[lane + 96];
            float mx = fmaxf(fmaxf(v0, v1), fmaxf(v2, v3));
#pragma unroll
            for (int o2 = 16; o2; o2 >>= 1) mx = fmaxf(mx, __shfl_xor_sync(0xffffffffu, mx, o2));
            v0 = __expf(v0 - mx); v1 = __expf(v1 - mx);
            v2 = __expf(v2 - mx); v3 = __expf(v3 - mx);
            float sum = v0 + v1 + v2 + v3;
#pragma unroll
            for (int o2 = 16; o2; o2 >>= 1) sum += __shfl_xor_sync(0xffffffffu, sum, o2);
            float invs = 1.0f / sum;
            row[lane]      = v0 * invs; row[lane + 32] = v1 * invs;
            row[lane + 64] = v2 * invs; row[lane + 96] = v3 * invs;
        }
        __syncthreads();

        // PV: 32x32 outputs
#pragma unroll 1
        for (int i = 0; i < 4; i++) {
            int e = tid + i * 256;
            int qq = e >> 5, d = e & 31;
            const float* prow = sc + qq * NK_;
            float acc = 0.0f;
#pragma unroll
            for (int kj = 0; kj < NK_; kj++) acc += prow[kj] * Vs[kj * 33 + d];
            o[((size_t)b * N_ + nb * NQ_ + qq) * CA_ + h * DH_ + d] = acc;
        }
        __syncthreads();
    }
}

// ---------------------------------------------------------------------------
// Host launch
// ---------------------------------------------------------------------------
extern "C" void kernel_launch(void* const* d_in, const int* in_sizes, int n_in,
                              void* d_out, int out_size)
{
    const float* a       = (const float*)d_in[0];
    const float* s       = (const float*)d_in[1];
    const float* z       = (const float*)d_in[2];
    const float* apb_gam = (const float*)d_in[3];
    const float* apb_Wg  = (const float*)d_in[4];
    const float* apb_bg  = (const float*)d_in[5];
    const float* apb_Wsk = (const float*)d_in[6];
    const float* Wq      = (const float*)d_in[7];
    const float* bq      = (const float*)d_in[8];
    const float* Wk      = (const float*)d_in[9];
    const float* Wv      = (const float*)d_in[10];
    const float* Wgate   = (const float*)d_in[11];
    const float* Wo      = (const float*)d_in[12];
    const float* gamma_z = (const float*)d_in[13];
    const float* Wz      = (const float*)d_in[14];
    const float* Ws_last = (const float*)d_in[15];
    const float* bs_last = (const float*)d_in[16];
    const float* ct_gam  = (const float*)d_in[17];
    const float* ct_Wg   = (const float*)d_in[18];
    const float* ct_bg   = (const float*)d_in[19];
    const float* ct_Wsk  = (const float*)d_in[20];
    const float* Wa1     = (const float*)d_in[21];
    const float* Wa2     = (const float*)d_in[22];
    const float* Wb      = (const float*)d_in[23];
    const float* Ws      = (const float*)d_in[24];
    const float* bsv     = (const float*)d_in[25];
    float* out = (float*)d_out;

    float* S = nullptr;
    cudaGetSymbolAddress((void**)&S, g_scratch);
    auto buf = [&](int i) { return S + (size_t)i * SLOT; };
    float* a_n   = buf(0);
    float* s_apb = buf(1);
    float* s_ct  = buf(2);
    float* gapb  = buf(3);
    float* kapb  = buf(4);
    float* gct   = buf(5);
    float* kct   = buf(6);
    float* glast = buf(7);
    float* sg    = buf(8);
    float* a1    = buf(9);
    float* a3    = buf(10);
    float* qb    = buf(11);
    float* kb    = buf(12);
    float* vb    = buf(13);
    float* gate  = buf(14);
    float* u1    = buf(15);  // M x 256 (slots 15-16)
    float* u2    = buf(17);  // M x 256 (slots 17-18)
    float* ctp   = buf(19);
    float* ob    = buf(20);

    // 1. LayerNorms
    ln_kernel<<<M_ / 8, 256>>>(a, s, apb_gam, ct_gam, a_n, s_apb, s_ct);

    dim3 g1(M_ / 128, 1), g2(M_ / 128, 2);
    // 2. adaLN + gate GEMMs
    gemm_kernel<<<g1, 256>>>(s_apb, nullptr, apb_Wg,  nullptr, gapb,  M_, 128, 128, 0, nullptr, nullptr);
    gemm_kernel<<<g1, 256>>>(s_apb, nullptr, apb_Wsk, nullptr, kapb,  M_, 128, 128, 0, nullptr, nullptr);
    gemm_kernel<<<g1, 256>>>(s_ct,  nullptr, ct_Wg,   nullptr, gct,   M_, 128, 128, 0, nullptr, nullptr);
    gemm_kernel<<<g1, 256>>>(s_ct,  nullptr, ct_Wsk,  nullptr, kct,   M_, 128, 128, 0, nullptr, nullptr);
    gemm_kernel<<<g1, 256>>>(s,     nullptr, Ws_last, nullptr, glast, M_, 128, 128, 0, nullptr, nullptr);
    gemm_kernel<<<g1, 256>>>(s,     nullptr, Ws,      nullptr, sg,    M_, 128, 128, 0, nullptr, nullptr);

    // 3. combine into a1 / a3 / gates
    combine1_kernel<<<(int)(SLOT / 4 / 256), 256>>>(gapb, kapb, gct, kct, glast, sg,
                                                    a_n, apb_bg, ct_bg, bs_last, bsv, a1, a3);

    // 4. QKV / gate / transition GEMMs
    gemm_kernel<<<g1, 256>>>(a1, nullptr, Wq,    bq,      qb,   M_, 128, 128, 0, nullptr, nullptr);
    gemm_kernel<<<g1, 256>>>(a1, nullptr, Wk,    nullptr, kb,   M_, 128, 128, 0, nullptr, nullptr);
    gemm_kernel<<<g1, 256>>>(a1, nullptr, Wv,    nullptr, vb,   M_, 128, 128, 0, nullptr, nullptr);
    gemm_kernel<<<g1, 256>>>(a1, nullptr, Wgate, nullptr, gate, M_, 128, 128, 1, nullptr, nullptr);
    gemm_kernel<<<g2, 256>>>(a3, nullptr, Wa1,   nullptr, u1,   M_, 256, 128, 0, nullptr, nullptr);
    gemm_kernel<<<g2, 256>>>(a3, nullptr, Wa2,   nullptr, u2,   M_, 256, 128, 0, nullptr, nullptr);

    // 5. t = silu(u1) * u2 (in place into u1)
    silu_kernel<<<(int)(2 * SLOT / 4 / 256), 256>>>(u1, u2);

    // 6. ct_out = sigmoid(s@Ws+bs) * (t @ Wb)
    gemm_kernel<<<g1, 256>>>(u1, nullptr, Wb, nullptr, ctp, M_, 128, 256, 2, sg, nullptr);

    // 7. fused bias + local attention
    cudaFuncSetAttribute(attn_kernel, cudaFuncAttributeMaxDynamicSharedMemorySize,
                         ATTN_SMEM_FLOATS * 4);
    attn_kernel<<<dim3(NB_, B_), 256, ATTN_SMEM_FLOATS * 4>>>(qb, kb, vb, z, gamma_z, Wz, ob);

    // 8. out = glast * ((gate*o) @ Wo) + ct_out
    gemm_kernel<<<g1, 256>>>(ob, gate, Wo, nullptr, out, M_, 128, 128, 3, glast, ctp);
}

// round 2
// speedup vs baseline: 1.6563x; 1.6563x over previous
#include <cuda_runtime.h>
#include <cstdint>

// ---------------------------------------------------------------------------
// AtomAttentionEncoder fused pipeline (round 2: tf32 tensor-core GEMMs)
// B=2, N=16384, CA=CS=128, CZ=16, H=4, NQ=32, NK=128, DH=32, NB=512
// ---------------------------------------------------------------------------

constexpr int B_  = 2;
constexpr int N_  = 16384;
constexpr int CA_ = 128;
constexpr int CZ_ = 16;
constexpr int H_  = 4;
constexpr int NQ_ = 32;
constexpr int NK_ = 128;
constexpr int DH_ = 32;
constexpr int NB_ = 512;

constexpr int    M_   = B_ * N_;               // 32768 tokens
constexpr size_t SLOT = (size_t)M_ * CA_;      // 4,194,304 floats = 16 MB

__device__ float g_scratch[21 * SLOT];

__device__ __forceinline__ float sigmoidf_(float x) { return 1.0f / (1.0f + __expf(-x)); }

__device__ __forceinline__ float tf32r_(float x) {
    uint32_t u;
    asm("cvt.rna.tf32.f32 %0, %1;" : "=r"(u) : "f"(x));
    return __uint_as_float(u);
}

#define MMA_TF32(cc, aa, bb)                                                   \
    asm volatile("mma.sync.aligned.m16n8k8.row.col.f32.tf32.tf32.f32 "         \
                 "{%0,%1,%2,%3}, {%4,%5,%6,%7}, {%8,%9}, {%0,%1,%2,%3};"       \
                 : "+f"(cc[0]), "+f"(cc[1]), "+f"(cc[2]), "+f"(cc[3])          \
                 : "r"(aa[0]), "r"(aa[1]), "r"(aa[2]), "r"(aa[3]),             \
                   "r"(bb[0]), "r"(bb[1]))

// ---------------------------------------------------------------------------
// LayerNorm kernel
// ---------------------------------------------------------------------------
__global__ void ln_kernel(const float* __restrict__ a, const float* __restrict__ s,
                          const float* __restrict__ apbg, const float* __restrict__ ctg,
                          float* __restrict__ a_n, float* __restrict__ s_apb,
                          float* __restrict__ s_ct)
{
    int warp = (blockIdx.x * blockDim.x + threadIdx.x) >> 5;
    int lane = threadIdx.x & 31;
    if (warp >= M_) return;
    size_t base = (size_t)warp * CA_;

    float4 av = ((const float4*)(a + base))[lane];
    float sum = av.x + av.y + av.z + av.w;
    float sq  = av.x * av.x + av.y * av.y + av.z * av.z + av.w * av.w;
#pragma unroll
    for (int o = 16; o; o >>= 1) {
        sum += __shfl_xor_sync(0xffffffffu, sum, o);
        sq  += __shfl_xor_sync(0xffffffffu, sq,  o);
    }
    float m   = sum * (1.0f / 128.0f);
    float inv = rsqrtf(sq * (1.0f / 128.0f) - m * m + 1e-5f);
    float4 ao;
    ao.x = (av.x - m) * inv; ao.y = (av.y - m) * inv;
    ao.z = (av.z - m) * inv; ao.w = (av.w - m) * inv;
    ((float4*)(a_n + base))[lane] = ao;

    float4 sv = ((const float4*)(s + base))[lane];
    float sums = sv.x + sv.y + sv.z + sv.w;
    float sqs  = sv.x * sv.x + sv.y * sv.y + sv.z * sv.z + sv.w * sv.w;
#pragma unroll
    for (int o = 16; o; o >>= 1) {
        sums += __shfl_xor_sync(0xffffffffu, sums, o);
        sqs  += __shfl_xor_sync(0xffffffffu, sqs,  o);
    }
    float ms   = sums * (1.0f / 128.0f);
    float invs = rsqrtf(sqs * (1.0f / 128.0f) - ms * ms + 1e-5f);
    float4 sn;
    sn.x = (sv.x - ms) * invs; sn.y = (sv.y - ms) * invs;
    sn.z = (sv.z - ms) * invs; sn.w = (sv.w - ms) * invs;

    float4 g1 = ((const float4*)apbg)[lane];
    float4 g2 = ((const float4*)ctg)[lane];
    float4 o1, o2;
    o1.x = sn.x * g1.x; o1.y = sn.y * g1.y; o1.z = sn.z * g1.z; o1.w = sn.w * g1.w;
    o2.x = sn.x * g2.x; o2.y = sn.y * g2.y; o2.z = sn.z * g2.z; o2.w = sn.w * g2.w;
    ((float4*)(s_apb + base))[lane] = o1;
    ((float4*)(s_ct  + base))[lane] = o2;
}

// ---------------------------------------------------------------------------
// tf32 tensor-core GEMM: C[M,N] = epilogue( (A .* Apre?) @ W + bias )
// ep: 0 none, 1 sigmoid, 2 C=e1*acc, 3 C=e1*acc+e2
// Tile 128x128, BK=32, 8 warps (2x4), warp tile 64x32, m16n8k8 tf32.
// ---------------------------------------------------------------------------
__global__ void __launch_bounds__(256) gemm_tc(
    const float* __restrict__ A, const float* __restrict__ Apre,
    const float* __restrict__ W, const float* __restrict__ bias,
    float* __restrict__ C, int M, int N, int K,
    int ep, const float* __restrict__ e1, const float* __restrict__ e2)
{
    __shared__ float As[128][36];   // stride 36: conflict-free frag loads
    __shared__ float Bs[32][136];   // stride 136

    int tid  = threadIdx.x;
    int warp = tid >> 5, lane = tid & 31;
    int wm = (warp >> 2) * 64;      // 0 / 64
    int wn = (warp & 3) * 32;       // 0..96
    int gid = lane >> 2, qid = lane & 3;
    int row0 = blockIdx.x * 128;
    int col0 = blockIdx.y * 128;

    float c[4][4][4];
#pragma unroll
    for (int mi = 0; mi < 4; mi++)
#pragma unroll
        for (int ni = 0; ni < 4; ni++)
#pragma unroll
            for (int r = 0; r < 4; r++) c[mi][ni][r] = 0.0f;

    for (int k0 = 0; k0 < K; k0 += 32) {
        // --- load A tile (128x32) ---
#pragma unroll
        for (int i = 0; i < 4; i++) {
            int e  = tid + i * 256;
            int r  = e >> 3;
            int c4 = (e & 7) << 2;
            float4 v = *(const float4*)(A + (size_t)(row0 + r) * K + k0 + c4);
            if (Apre) {
                float4 p = *(const float4*)(Apre + (size_t)(row0 + r) * K + k0 + c4);
                v.x *= p.x; v.y *= p.y; v.z *= p.z; v.w *= p.w;
            }
            float4 t;
            t.x = tf32r_(v.x); t.y = tf32r_(v.y); t.z = tf32r_(v.z); t.w = tf32r_(v.w);
            *(float4*)&As[r][c4] = t;
        }
        // --- load B tile (32x128) ---
#pragma unroll
        for (int i = 0; i < 4; i++) {
            int e  = tid + i * 256;
            int kk = e >> 5;
            int n4 = (e & 31) << 2;
            float4 v = *(const float4*)(W + (size_t)(k0 + kk) * N + col0 + n4);
            float4 t;
            t.x = tf32r_(v.x); t.y = tf32r_(v.y); t.z = tf32r_(v.z); t.w = tf32r_(v.w);
            *(float4*)&Bs[kk][n4] = t;
        }
        __syncthreads();

#pragma unroll
        for (int ks = 0; ks < 4; ks++) {
            int kb = ks * 8;
            uint32_t af[4][4], bf[4][2];
#pragma unroll
            for (int mi = 0; mi < 4; mi++) {
                int r = wm + mi * 16 + gid;
                af[mi][0] = __float_as_uint(As[r    ][kb + qid]);
                af[mi][1] = __float_as_uint(As[r + 8][kb + qid]);
                af[mi][2] = __float_as_uint(As[r    ][kb + qid + 4]);
                af[mi][3] = __float_as_uint(As[r + 8][kb + qid + 4]);
            }
#pragma unroll
            for (int ni = 0; ni < 4; ni++) {
                int cc = wn + ni * 8 + gid;
                bf[ni][0] = __float_as_uint(Bs[kb + qid    ][cc]);
                bf[ni][1] = __float_as_uint(Bs[kb + qid + 4][cc]);
            }
#pragma unroll
            for (int mi = 0; mi < 4; mi++)
#pragma unroll
                for (int ni = 0; ni < 4; ni++)
                    MMA_TF32(c[mi][ni], af[mi], bf[ni]);
        }
        __syncthreads();
    }

    // --- epilogue ---
#pragma unroll
    for (int mi = 0; mi < 4; mi++) {
#pragma unroll
        for (int ni = 0; ni < 4; ni++) {
            int rA = row0 + wm + mi * 16 + gid;
            int cc = col0 + wn + ni * 8 + qid * 2;
            float b0 = bias ? bias[cc]     : 0.0f;
            float b1 = bias ? bias[cc + 1] : 0.0f;
#pragma unroll
            for (int h = 0; h < 2; h++) {
                size_t idx = (size_t)(rA + h * 8) * N + cc;
                float v0 = c[mi][ni][h * 2 + 0] + b0;
                float v1 = c[mi][ni][h * 2 + 1] + b1;
                if (ep == 1)      { v0 = sigmoidf_(v0); v1 = sigmoidf_(v1); }
                else if (ep == 2) { v0 *= e1[idx]; v1 *= e1[idx + 1]; }
                else if (ep == 3) { v0 = e1[idx] * v0 + e2[idx];
                                    v1 = e1[idx + 1] * v1 + e2[idx + 1]; }
                *(float2*)(C + idx) = make_float2(v0, v1);
            }
        }
    }
}

// ---------------------------------------------------------------------------
// Combine: a1/a3 + the two raw-s sigmoid gates (in place).
// ---------------------------------------------------------------------------
__global__ void combine1_kernel(
    const float* __restrict__ gapb, const float* __restrict__ kapb,
    const float* __restrict__ gct,  const float* __restrict__ kct,
    float* __restrict__ glast, float* __restrict__ sg,
    const float* __restrict__ a_n,
    const float* __restrict__ bg, const float* __restrict__ ctbg,
    const float* __restrict__ bsl, const float* __restrict__ bsv,
    float* __restrict__ a1, float* __restrict__ a3)
{
    size_t i = (size_t)blockIdx.x * blockDim.x + threadIdx.x;
    int c = (int)(i & 31) * 4;
    float4 van = ((const float4*)a_n)[i];
    float4 v1, v2, o1;

    v1 = ((const float4*)gapb)[i];
    v2 = ((const float4*)kapb)[i];
    o1.x = sigmoidf_(v1.x + bg[c + 0]) * van.x + v2.x;
    o1.y = sigmoidf_(v1.y + bg[c + 1]) * van.y + v2.y;
    o1.z = sigmoidf_(v1.z + bg[c + 2]) * van.z + v2.z;
    o1.w = sigmoidf_(v1.w + bg[c + 3]) * van.w + v2.w;
    ((float4*)a1)[i] = o1;

    v1 = ((const float4*)gct)[i];
    v2 = ((const float4*)kct)[i];
    o1.x = sigmoidf_(v1.x + ctbg[c + 0]) * van.x + v2.x;
    o1.y = sigmoidf_(v1.y + ctbg[c + 1]) * van.y + v2.y;
    o1.z = sigmoidf_(v1.z + ctbg[c + 2]) * van.z + v2.z;
    o1.w = sigmoidf_(v1.w + ctbg[c + 3]) * van.w + v2.w;
    ((float4*)a3)[i] = o1;

    v1 = ((const float4*)glast)[i];
    o1.x = sigmoidf_(v1.x + bsl[c + 0]);
    o1.y = sigmoidf_(v1.y + bsl[c + 1]);
    o1.z = sigmoidf_(v1.z + bsl[c + 2]);
    o1.w = sigmoidf_(v1.w + bsl[c + 3]);
    ((float4*)glast)[i] = o1;

    v1 = ((const float4*)sg)[i];
    o1.x = sigmoidf_(v1.x + bsv[c + 0]);
    o1.y = sigmoidf_(v1.y + bsv[c + 1]);
    o1.z = sigmoidf_(v1.z + bsv[c + 2]);
    o1.w = sigmoidf_(v1.w + bsv[c + 3]);
    ((float4*)sg)[i] = o1;
}

__global__ void silu_kernel(float* __restrict__ u1, const float* __restrict__ u2)
{
    size_t i = (size_t)blockIdx.x * blockDim.x + threadIdx.x;
    float4 x = ((const float4*)u1)[i];
    float4 y = ((const float4*)u2)[i];
    float4 o;
    o.x = x.x * sigmoidf_(x.x) * y.x;
    o.y = x.y * sigmoidf_(x.y) * y.y;
    o.z = x.z * sigmoidf_(x.z) * y.z;
    o.w = x.w * sigmoidf_(x.w) * y.w;
    ((float4*)u1)[i] = o;
}

// ---------------------------------------------------------------------------
// Fused local attention (unchanged from round 1).
// ---------------------------------------------------------------------------
constexpr int ATTN_SMEM_FLOATS = H_ * NQ_ * NK_ + NQ_ * CA_ + 2 * NK_ * 33;  // 28928

__global__ void __launch_bounds__(256) attn_kernel(
    const float* __restrict__ q, const float* __restrict__ kg,
    const float* __restrict__ vg, const float* __restrict__ z,
    const float* __restrict__ gamma_z, const float* __restrict__ Wz,
    float* __restrict__ o)
{
    extern __shared__ float sm[];
    float* biasS = sm;
    float* Qs = biasS + H_ * NQ_ * NK_;
    float* Ks = Qs + NQ_ * CA_;
    float* Vs = Ks + NK_ * 33;
    __shared__ float gzs[CZ_];
    __shared__ float wzs[CZ_ * H_];

    int tid = threadIdx.x;
    int nb = blockIdx.x, b = blockIdx.y;
    if (tid < CZ_)      gzs[tid] = gamma_z[tid];
    if (tid < CZ_ * H_) wzs[tid] = Wz[tid];

    for (int e = tid; e < NQ_ * CA_ / 4; e += 256) {
        int qq = e >> 5;
        int c  = (e & 31) * 4;
        ((float4*)Qs)[e] = *(const float4*)(q + ((size_t)b * N_ + nb * NQ_ + qq) * CA_ + c);
    }
    __syncthreads();

    const float* zb = z + ((size_t)(b * NB_ + nb)) * NQ_ * NK_ * CZ_;
#pragma unroll 1
    for (int i = 0; i < 16; i++) {
        int p = tid + i * 256;
        const float4* zp = (const float4*)(zb + (size_t)p * CZ_);
        float4 z0 = zp[0], z1 = zp[1], z2 = zp[2], z3 = zp[3];
        float zv[16] = {z0.x, z0.y, z0.z, z0.w, z1.x, z1.y, z1.z, z1.w,
                        z2.x, z2.y, z2.z, z2.w, z3.x, z3.y, z3.z, z3.w};
        float mm = 0.0f;
#pragma unroll
        for (int c = 0; c < 16; c++) mm += zv[c];
        mm *= (1.0f / 16.0f);
        float ss2 = 0.0f;
#pragma unroll
        for (int c = 0; c < 16; c++) { float d = zv[c] - mm; ss2 += d * d; }
        float inv = rsqrtf(ss2 * (1.0f / 16.0f) + 1e-5f);
        float bh0 = 0, bh1 = 0, bh2 = 0, bh3 = 0;
#pragma unroll
        for (int c = 0; c < 16; c++) {
            float zn = (zv[c] - mm) * inv * gzs[c];
            bh0 += zn * wzs[c * 4 + 0];
            bh1 += zn * wzs[c * 4 + 1];
            bh2 += zn * wzs[c * 4 + 2];
            bh3 += zn * wzs[c * 4 + 3];
        }
        biasS[0 * 4096 + p] = bh0;
        biasS[1 * 4096 + p] = bh1;
        biasS[2 * 4096 + p] = bh2;
        biasS[3 * 4096 + p] = bh3;
    }
    __syncthreads();

    int kbase = nb * NQ_ - (NK_ - NQ_) / 2;
    int warp = tid >> 5, lane = tid & 31;

    for (int h = 0; h < H_; h++) {
        for (int e = tid; e < NK_ * DH_ / 4; e += 256) {
            int j = e >> 3;
            int d = (e & 7) * 4;
            int t = kbase + j;
            t = t < 0 ? 0 : (t >= N_ ? N_ - 1 : t);
            size_t off = ((size_t)b * N_ + t) * CA_ + h * DH_ + d;
            float4 kv = *(const float4*)(kg + off);
            Ks[j * 33 + d + 0] = kv.x; Ks[j * 33 + d + 1] = kv.y;
            Ks[j * 33 + d + 2] = kv.z; Ks[j * 33 + d + 3] = kv.w;
            float4 vv = *(const float4*)(vg + off);
            Vs[j * 33 + d + 0] = vv.x; Vs[j * 33 + d + 1] = vv.y;
            Vs[j * 33 + d + 2] = vv.z; Vs[j * 33 + d + 3] = vv.w;
        }
        __syncthreads();

        float* sc = biasS + h * (NQ_ * NK_);
#pragma unroll 1
        for (int i = 0; i < 16; i++) {
            int p = tid + i * 256;
            int qq = p >> 7, kj = p & 127;
            const float* qrow = Qs + qq * CA_ + h * DH_;
            const float* krow = Ks + kj * 33;
            float acc = 0.0f;
#pragma unroll
            for (int d = 0; d < 32; d++) acc += qrow[d] * krow[d];
            int t = kbase + kj;
            float svv = (t >= 0 && t < N_) ? acc * 0.17677669529663687f + sc[p]
                                           : -1e9f;
            sc[p] = svv;
        }
        __syncthreads();

#pragma unroll
        for (int rr = 0; rr < 4; rr++) {
            int r = warp * 4 + rr;
            float* row = sc + r * NK_;
            float v0 = row[lane], v1 = row[lane + 32], v2 = row[lane + 64], v3 = row[lane + 96];
            float mx = fmaxf(fmaxf(v0, v1), fmaxf(v2, v3));
#pragma unroll
            for (int o2 = 16; o2; o2 >>= 1) mx = fmaxf(mx, __shfl_xor_sync(0xffffffffu, mx, o2));
            v0 = __expf(v0 - mx); v1 = __expf(v1 - mx);
            v2 = __expf(v2 - mx); v3 = __expf(v3 - mx);
            float sum = v0 + v1 + v2 + v3;
#pragma unroll
            for (int o2 = 16; o2; o2 >>= 1) sum += __shfl_xor_sync(0xffffffffu, sum, o2);
            float invs = 1.0f / sum;
            row[lane]      = v0 * invs; row[lane + 32] = v1 * invs;
            row[lane + 64] = v2 * invs; row[lane + 96] = v3 * invs;
        }
        __syncthreads();

#pragma unroll 1
        for (int i = 0; i < 4; i++) {
            int e = tid + i * 256;
            int qq = e >> 5, d = e & 31;
            const float* prow = sc + qq * NK_;
            float acc = 0.0f;
#pragma unroll
            for (int kj = 0; kj < NK_; kj++) acc += prow[kj] * Vs[kj * 33 + d];
            o[((size_t)b * N_ + nb * NQ_ + qq) * CA_ + h * DH_ + d] = acc;
        }
        __syncthreads();
    }
}

// ---------------------------------------------------------------------------
// Host launch
// ---------------------------------------------------------------------------
extern "C" void kernel_launch(void* const* d_in, const int* in_sizes, int n_in,
                              void* d_out, int out_size)
{
    const float* a       = (const float*)d_in[0];
    const float* s       = (const float*)d_in[1];
    const float* z       = (const float*)d_in[2];
    const float* apb_gam = (const float*)d_in[3];
    const float* apb_Wg  = (const float*)d_in[4];
    const float* apb_bg  = (const float*)d_in[5];
    const float* apb_Wsk = (const float*)d_in[6];
    const float* Wq      = (const float*)d_in[7];
    const float* bq      = (const float*)d_in[8];
    const float* Wk      = (const float*)d_in[9];
    const float* Wv      = (const float*)d_in[10];
    const float* Wgate   = (const float*)d_in[11];
    const float* Wo      = (const float*)d_in[12];
    const float* gamma_z = (const float*)d_in[13];
    const float* Wz      = (const float*)d_in[14];
    const float* Ws_last = (const float*)d_in[15];
    const float* bs_last = (const float*)d_in[16];
    const float* ct_gam  = (const float*)d_in[17];
    const float* ct_Wg   = (const float*)d_in[18];
    const float* ct_bg   = (const float*)d_in[19];
    const float* ct_Wsk  = (const float*)d_in[20];
    const float* Wa1     = (const float*)d_in[21];
    const float* Wa2     = (const float*)d_in[22];
    const float* Wb      = (const float*)d_in[23];
    const float* Ws      = (const float*)d_in[24];
    const float* bsv     = (const float*)d_in[25];
    float* out = (float*)d_out;

    float* S = nullptr;
    cudaGetSymbolAddress((void**)&S, g_scratch);
    auto buf = [&](int i) { return S + (size_t)i * SLOT; };
    float* a_n   = buf(0);
    float* s_apb = buf(1);
    float* s_ct  = buf(2);
    float* gapb  = buf(3);
    float* kapb  = buf(4);
    float* gct   = buf(5);
    float* kct   = buf(6);
    float* glast = buf(7);
    float* sg    = buf(8);
    float* a1    = buf(9);
    float* a3    = buf(10);
    float* qb    = buf(11);
    float* kb    = buf(12);
    float* vb    = buf(13);
    float* gate  = buf(14);
    float* u1    = buf(15);  // M x 256
    float* u2    = buf(17);  // M x 256
    float* ctp   = buf(19);
    float* ob    = buf(20);

    ln_kernel<<<M_ / 8, 256>>>(a, s, apb_gam, ct_gam, a_n, s_apb, s_ct);

    dim3 g1(M_ / 128, 1), g2(M_ / 128, 2);
    gemm_tc<<<g1, 256>>>(s_apb, nullptr, apb_Wg,  nullptr, gapb,  M_, 128, 128, 0, nullptr, nullptr);
    gemm_tc<<<g1, 256>>>(s_apb, nullptr, apb_Wsk, nullptr, kapb,  M_, 128, 128, 0, nullptr, nullptr);
    gemm_tc<<<g1, 256>>>(s_ct,  nullptr, ct_Wg,   nullptr, gct,   M_, 128, 128, 0, nullptr, nullptr);
    gemm_tc<<<g1, 256>>>(s_ct,  nullptr, ct_Wsk,  nullptr, kct,   M_, 128, 128, 0, nullptr, nullptr);
    gemm_tc<<<g1, 256>>>(s,     nullptr, Ws_last, nullptr, glast, M_, 128, 128, 0, nullptr, nullptr);
    gemm_tc<<<g1, 256>>>(s,     nullptr, Ws,      nullptr, sg,    M_, 128, 128, 0, nullptr, nullptr);

    combine1_kernel<<<(int)(SLOT / 4 / 256), 256>>>(gapb, kapb, gct, kct, glast, sg,
                                                    a_n, apb_bg, ct_bg, bs_last, bsv, a1, a3);

    gemm_tc<<<g1, 256>>>(a1, nullptr, Wq,    bq,      qb,   M_, 128, 128, 0, nullptr, nullptr);
    gemm_tc<<<g1, 256>>>(a1, nullptr, Wk,    nullptr, kb,   M_, 128, 128, 0, nullptr, nullptr);
    gemm_tc<<<g1, 256>>>(a1, nullptr, Wv,    nullptr, vb,   M_, 128, 128, 0, nullptr, nullptr);
    gemm_tc<<<g1, 256>>>(a1, nullptr, Wgate, nullptr, gate, M_, 128, 128, 1, nullptr, nullptr);
    gemm_tc<<<g2, 256>>>(a3, nullptr, Wa1,   nullptr, u1,   M_, 256, 128, 0, nullptr, nullptr);
    gemm_tc<<<g2, 256>>>(a3, nullptr, Wa2,   nullptr, u2,   M_, 256, 128, 0, nullptr, nullptr);

    silu_kernel<<<(int)(2 * SLOT / 4 / 256), 256>>>(u1, u2);

    gemm_tc<<<g1, 256>>>(u1, nullptr, Wb, nullptr, ctp, M_, 128, 256, 2, sg, nullptr);

    cudaFuncSetAttribute(attn_kernel, cudaFuncAttributeMaxDynamicSharedMemorySize,
                         ATTN_SMEM_FLOATS * 4);
    attn_kernel<<<dim3(NB_, B_), 256, ATTN_SMEM_FLOATS * 4>>>(qb, kb, vb, z, gamma_z, Wz, ob);

    gemm_tc<<<g1, 256>>>(ob, gate, Wo, nullptr, out, M_, 128, 128, 3, glast, ctp);
}

// round 4
// speedup vs baseline: 2.0868x; 1.2599x over previous
#include <cuda_runtime.h>
#include <cstdint>

// ---------------------------------------------------------------------------
// AtomAttentionEncoder fused pipeline (round 4 = round 3 + scratch OOB fix)
// tf32 tensor-core GEMMs with cp.async double-buffering + 2 CTA/SM,
// batched weight segments, LDS-efficient attention.
// B=2, N=16384, CA=CS=128, CZ=16, H=4, NQ=32, NK=128, DH=32, NB=512
// ---------------------------------------------------------------------------

constexpr int B_  = 2;
constexpr int N_  = 16384;
constexpr int CA_ = 128;
constexpr int CZ_ = 16;
constexpr int H_  = 4;
constexpr int NQ_ = 32;
constexpr int NK_ = 128;
constexpr int DH_ = 32;
constexpr int NB_ = 512;

constexpr int    M_   = B_ * N_;               // 32768 tokens
constexpr size_t SLOT = (size_t)M_ * CA_;      // 4,194,304 floats = 16 MB

// 21 activation slots + 1 weight slot + 1 slot for s_r
__device__ float g_scratch[23 * SLOT];

__device__ __forceinline__ float sigmoidf_(float x) { return 1.0f / (1.0f + __expf(-x)); }

__device__ __forceinline__ float tf32r_(float x) {
    uint32_t u;
    asm("cvt.rna.tf32.f32 %0, %1;" : "=r"(u) : "f"(x));
    return __uint_as_float(u);
}

#define MMA_TF32(cc, aa, bb)                                                   \
    asm volatile("mma.sync.aligned.m16n8k8.row.col.f32.tf32.tf32.f32 "         \
                 "{%0,%1,%2,%3}, {%4,%5,%6,%7}, {%8,%9}, {%0,%1,%2,%3};"       \
                 : "+f"(cc[0]), "+f"(cc[1]), "+f"(cc[2]), "+f"(cc[3])          \
                 : "r"(aa[0]), "r"(aa[1]), "r"(aa[2]), "r"(aa[3]),             \
                   "r"(bb[0]), "r"(bb[1]))

__device__ __forceinline__ void cp_async16(uint32_t smem_addr, const void* gptr) {
    asm volatile("cp.async.cg.shared.global [%0], [%1], 16;\n"
                 :: "r"(smem_addr), "l"(gptr));
}
__device__ __forceinline__ void cp_commit() { asm volatile("cp.async.commit_group;\n"); }
__device__ __forceinline__ void cp_wait1()  { asm volatile("cp.async.wait_group 1;\n"); }

// ---------------------------------------------------------------------------
// Weight tf32 pre-rounding: grid.y selects matrix
// ---------------------------------------------------------------------------
struct WPack {
    const float* src[14];
    float*       dst[14];
    int          n[14];
};
__global__ void cvtw_kernel(WPack p)
{
    int y = blockIdx.y;
    int n = p.n[y];
    const float* s = p.src[y];
    float* d = p.dst[y];
    for (int i = blockIdx.x * 256 + threadIdx.x; i < n; i += gridDim.x * 256)
        d[i] = tf32r_(s[i]);
}

// ---------------------------------------------------------------------------
// LayerNorm: a_n = LN(a); s_apb = tf32(LN(s)*g_apb); s_ct = tf32(LN(s)*g_ct);
// s_r = tf32(s)
// ---------------------------------------------------------------------------
__global__ void ln_kernel(const float* __restrict__ a, const float* __restrict__ s,
                          const float* __restrict__ apbg, const float* __restrict__ ctg,
                          float* __restrict__ a_n, float* __restrict__ s_apb,
                          float* __restrict__ s_ct, float* __restrict__ s_r)
{
    int warp = (blockIdx.x * blockDim.x + threadIdx.x) >> 5;
    int lane = threadIdx.x & 31;
    if (warp >= M_) return;
    size_t base = (size_t)warp * CA_;

    float4 av = ((const float4*)(a + base))[lane];
    float sum = av.x + av.y + av.z + av.w;
    float sq  = av.x * av.x + av.y * av.y + av.z * av.z + av.w * av.w;
#pragma unroll
    for (int o = 16; o; o >>= 1) {
        sum += __shfl_xor_sync(0xffffffffu, sum, o);
        sq  += __shfl_xor_sync(0xffffffffu, sq,  o);
    }
    float m   = sum * (1.0f / 128.0f);
    float inv = rsqrtf(sq * (1.0f / 128.0f) - m * m + 1e-5f);
    float4 ao;
    ao.x = (av.x - m) * inv; ao.y = (av.y - m) * inv;
    ao.z = (av.z - m) * inv; ao.w = (av.w - m) * inv;
    ((float4*)(a_n + base))[lane] = ao;

    float4 sv = ((const float4*)(s + base))[lane];
    float4 sr;
    sr.x = tf32r_(sv.x); sr.y = tf32r_(sv.y); sr.z = tf32r_(sv.z); sr.w = tf32r_(sv.w);
    ((float4*)(s_r + base))[lane] = sr;

    float sums = sv.x + sv.y + sv.z + sv.w;
    float sqs  = sv.x * sv.x + sv.y * sv.y + sv.z * sv.z + sv.w * sv.w;
#pragma unroll
    for (int o = 16; o; o >>= 1) {
        sums += __shfl_xor_sync(0xffffffffu, sums, o);
        sqs  += __shfl_xor_sync(0xffffffffu, sqs,  o);
    }
    float ms   = sums * (1.0f / 128.0f);
    float invs = rsqrtf(sqs * (1.0f / 128.0f) - ms * ms + 1e-5f);
    float4 sn;
    sn.x = (sv.x - ms) * invs; sn.y = (sv.y - ms) * invs;
    sn.z = (sv.z - ms) * invs; sn.w = (sv.w - ms) * invs;

    float4 g1 = ((const float4*)apbg)[lane];
    float4 g2 = ((const float4*)ctg)[lane];
    float4 o1, o2;
    o1.x = tf32r_(sn.x * g1.x); o1.y = tf32r_(sn.y * g1.y);
    o1.z = tf32r_(sn.z * g1.z); o1.w = tf32r_(sn.w * g1.w);
    o2.x = tf32r_(sn.x * g2.x); o2.y = tf32r_(sn.y * g2.y);
    o2.z = tf32r_(sn.z * g2.z); o2.w = tf32r_(sn.w * g2.w);
    ((float4*)(s_apb + base))[lane] = o1;
    ((float4*)(s_ct  + base))[lane] = o2;
}

// ---------------------------------------------------------------------------
// Multi-segment tf32 GEMM. grid.y = segment; each segment is a 128-col output.
// ep: 0 none, 1 sigmoid(acc+bias), 2 C=e1*acc, 3 C=e1*acc+e2
// ---------------------------------------------------------------------------
struct GemmSegs {
    const float* W[4];
    const float* bias[4];
    float*       C[4];
    const float* e1[4];
    const float* e2[4];
    int          ldW[4];
    int          ldC[4];
    int          ep[4];
};

constexpr int ASZ = 128 * 36;   // floats per A stage
constexpr int BSZ = 32 * 136;   // floats per B stage
constexpr int GEMM_SMEM = (2 * ASZ + 2 * BSZ) * 4;  // 71680 bytes

__global__ void __launch_bounds__(256, 2) gemm_tc(
    const float* __restrict__ A, const float* __restrict__ Apre,
    int K, int use_async, GemmSegs segs)
{
    extern __shared__ float sm[];
    float* AsBase = sm;
    float* BsBase = sm + 2 * ASZ;

    int tid  = threadIdx.x;
    int warp = tid >> 5, lane = tid & 31;
    int wm = (warp >> 2) * 64;
    int wn = (warp & 3) * 32;
    int gid = lane >> 2, qid = lane & 3;
    int row0 = blockIdx.x * 128;
    int y = blockIdx.y;
    const float* W = segs.W[y];
    int ldW = segs.ldW[y];
    int KT = K >> 5;

    uint32_t smBase;
    asm("{ .reg .u64 t; cvta.to.shared.u64 t, %1; cvt.u32.u64 %0, t; }"
        : "=r"(smBase) : "l"(sm));

    auto loadA = [&](int kt, int st) {
        float* As = AsBase + st * ASZ;
        if (use_async) {
#pragma unroll
            for (int i = 0; i < 4; i++) {
                int e  = tid + i * 256;
                int r  = e >> 3;
                int c4 = (e & 7) << 2;
                uint32_t dst = smBase + (uint32_t)(st * ASZ + r * 36 + c4) * 4u;
                cp_async16(dst, A + (size_t)(row0 + r) * K + kt * 32 + c4);
            }
        } else {
#pragma unroll
            for (int i = 0; i < 4; i++) {
                int e  = tid + i * 256;
                int r  = e >> 3;
                int c4 = (e & 7) << 2;
                float4 v = *(const float4*)(A + (size_t)(row0 + r) * K + kt * 32 + c4);
                if (Apre) {
                    float4 p = *(const float4*)(Apre + (size_t)(row0 + r) * K + kt * 32 + c4);
                    v.x *= p.x; v.y *= p.y; v.z *= p.z; v.w *= p.w;
                }
                float4 t;
                t.x = tf32r_(v.x); t.y = tf32r_(v.y); t.z = tf32r_(v.z); t.w = tf32r_(v.w);
                *(float4*)&As[r * 36 + c4] = t;
            }
        }
    };
    auto loadB = [&](int kt, int st) {
        float* Bs = BsBase + st * BSZ;
        if (use_async) {
#pragma unroll
            for (int i = 0; i < 4; i++) {
                int e  = tid + i * 256;
                int kk = e >> 5;
                int n4 = (e & 31) << 2;
                uint32_t dst = smBase + (uint32_t)(2 * ASZ + st * BSZ + kk * 136 + n4) * 4u;
                cp_async16(dst, W + (size_t)(kt * 32 + kk) * ldW + n4);
            }
        } else {
#pragma unroll
            for (int i = 0; i < 4; i++) {
                int e  = tid + i * 256;
                int kk = e >> 5;
                int n4 = (e & 31) << 2;
                float4 v = *(const float4*)(W + (size_t)(kt * 32 + kk) * ldW + n4);
                float4 t;
                t.x = tf32r_(v.x); t.y = tf32r_(v.y); t.z = tf32r_(v.z); t.w = tf32r_(v.w);
                *(float4*)&Bs[kk * 136 + n4] = t;
            }
        }
    };

    float c[4][4][4];
#pragma unroll
    for (int mi = 0; mi < 4; mi++)
#pragma unroll
        for (int ni = 0; ni < 4; ni++)
#pragma unroll
            for (int r = 0; r < 4; r++) c[mi][ni][r] = 0.0f;

    loadA(0, 0); loadB(0, 0);
    if (use_async) cp_commit();
    if (KT > 1) {
        loadA(1, 1); loadB(1, 1);
        if (use_async) cp_commit();
    }

    for (int kt = 0; kt < KT; kt++) {
        if (use_async) cp_wait1();
        __syncthreads();
        int st = kt & 1;
        const float* As = AsBase + st * ASZ;
        const float* Bs = BsBase + st * BSZ;
#pragma unroll
        for (int ks = 0; ks < 4; ks++) {
            int kb = ks * 8;
            uint32_t af[4][4], bf[4][2];
#pragma unroll
            for (int mi = 0; mi < 4; mi++) {
                int r = wm + mi * 16 + gid;
                af[mi][0] = __float_as_uint(As[r * 36 + kb + qid]);
                af[mi][1] = __float_as_uint(As[(r + 8) * 36 + kb + qid]);
                af[mi][2] = __float_as_uint(As[r * 36 + kb + qid + 4]);
                af[mi][3] = __float_as_uint(As[(r + 8) * 36 + kb + qid + 4]);
            }
#pragma unroll
            for (int ni = 0; ni < 4; ni++) {
                int cc = wn + ni * 8 + gid;
                bf[ni][0] = __float_as_uint(Bs[(kb + qid) * 136 + cc]);
                bf[ni][1] = __float_as_uint(Bs[(kb + qid + 4) * 136 + cc]);
            }
#pragma unroll
            for (int mi = 0; mi < 4; mi++)
#pragma unroll
                for (int ni = 0; ni < 4; ni++)
                    MMA_TF32(c[mi][ni], af[mi], bf[ni]);
        }
        __syncthreads();
        if (kt + 2 < KT) { loadA(kt + 2, st); loadB(kt + 2, st); }
        if (use_async) cp_commit();
    }

    const float* bias = segs.bias[y];
    float* C = segs.C[y];
    const float* e1 = segs.e1[y];
    const float* e2 = segs.e2[y];
    int ldC = segs.ldC[y];
    int ep  = segs.ep[y];

#pragma unroll
    for (int mi = 0; mi < 4; mi++) {
#pragma unroll
        for (int ni = 0; ni < 4; ni++) {
            int rA = row0 + wm + mi * 16 + gid;
            int cc = wn + ni * 8 + qid * 2;
            float b0 = bias ? bias[cc]     : 0.0f;
            float b1 = bias ? bias[cc + 1] : 0.0f;
#pragma unroll
            for (int h = 0; h < 2; h++) {
                size_t idx = (size_t)(rA + h * 8) * ldC + cc;
                float v0 = c[mi][ni][h * 2 + 0] + b0;
                float v1 = c[mi][ni][h * 2 + 1] + b1;
                if (ep == 1)      { v0 = sigmoidf_(v0); v1 = sigmoidf_(v1); }
                else if (ep == 2) { v0 *= e1[idx]; v1 *= e1[idx + 1]; }
                else if (ep == 3) { v0 = e1[idx] * v0 + e2[idx];
                                    v1 = e1[idx + 1] * v1 + e2[idx + 1]; }
                *(float2*)(C + idx) = make_float2(v0, v1);
            }
        }
    }
}

// ---------------------------------------------------------------------------
// Combine: a1 = tf32(gapb*a_n + kapb); a3 = tf32(gct*a_n + kct)
// ---------------------------------------------------------------------------
__global__ void combine1_kernel(
    const float* __restrict__ gapb, const float* __restrict__ kapb,
    const float* __restrict__ gct,  const float* __restrict__ kct,
    const float* __restrict__ a_n,
    float* __restrict__ a1, float* __restrict__ a3)
{
    size_t i = (size_t)blockIdx.x * blockDim.x + threadIdx.x;
    float4 van = ((const float4*)a_n)[i];
    float4 v1, v2, o1;

    v1 = ((const float4*)gapb)[i];
    v2 = ((const float4*)kapb)[i];
    o1.x = tf32r_(v1.x * van.x + v2.x);
    o1.y = tf32r_(v1.y * van.y + v2.y);
    o1.z = tf32r_(v1.z * van.z + v2.z);
    o1.w = tf32r_(v1.w * van.w + v2.w);
    ((float4*)a1)[i] = o1;

    v1 = ((const float4*)gct)[i];
    v2 = ((const float4*)kct)[i];
    o1.x = tf32r_(v1.x * van.x + v2.x);
    o1.y = tf32r_(v1.y * van.y + v2.y);
    o1.z = tf32r_(v1.z * van.z + v2.z);
    o1.w = tf32r_(v1.w * van.w + v2.w);
    ((float4*)a3)[i] = o1;
}

// t = tf32(silu(u1) * u2) in place into u1 (M x 256)
__global__ void silu_kernel(float* __restrict__ u1, const float* __restrict__ u2)
{
    size_t i = (size_t)blockIdx.x * blockDim.x + threadIdx.x;
    float4 x = ((const float4*)u1)[i];
    float4 y = ((const float4*)u2)[i];
    float4 o;
    o.x = tf32r_(x.x * sigmoidf_(x.x) * y.x);
    o.y = tf32r_(x.y * sigmoidf_(x.y) * y.y);
    o.z = tf32r_(x.z * sigmoidf_(x.z) * y.z);
    o.w = tf32r_(x.w * sigmoidf_(x.w) * y.w);
    ((float4*)u1)[i] = o;
}

// ---------------------------------------------------------------------------
// Fused local attention, LDS-efficient version.
// ---------------------------------------------------------------------------
constexpr int ATTN_SMEM_FLOATS = H_ * NQ_ * NK_ + NQ_ * CA_ + 2 * NK_ * 33;  // 28928

__global__ void __launch_bounds__(256) attn_kernel(
    const float* __restrict__ q, const float* __restrict__ kg,
    const float* __restrict__ vg, const float* __restrict__ z,
    const float* __restrict__ gamma_z, const float* __restrict__ Wz,
    float* __restrict__ o)
{
    extern __shared__ float sm[];
    float* biasS = sm;
    float* Qs = biasS + H_ * NQ_ * NK_;
    float* Ks = Qs + NQ_ * CA_;
    float* Vs = Ks + NK_ * 33;
    __shared__ float gzs[CZ_];
    __shared__ float wzs[CZ_ * H_];

    int tid = threadIdx.x;
    int nb = blockIdx.x, b = blockIdx.y;
    if (tid < CZ_)      gzs[tid] = gamma_z[tid];
    if (tid < CZ_ * H_) wzs[tid] = Wz[tid];

    for (int e = tid; e < NQ_ * CA_ / 4; e += 256) {
        int qq = e >> 5;
        int c  = (e & 31) * 4;
        ((float4*)Qs)[e] = *(const float4*)(q + ((size_t)b * N_ + nb * NQ_ + qq) * CA_ + c);
    }
    __syncthreads();

    const float* zb = z + ((size_t)(b * NB_ + nb)) * NQ_ * NK_ * CZ_;
#pragma unroll 1
    for (int i = 0; i < 16; i++) {
        int p = tid + i * 256;
        const float4* zp = (const float4*)(zb + (size_t)p * CZ_);
        float4 z0 = zp[0], z1 = zp[1], z2 = zp[2], z3 = zp[3];
        float zv[16] = {z0.x, z0.y, z0.z, z0.w, z1.x, z1.y, z1.z, z1.w,
                        z2.x, z2.y, z2.z, z2.w, z3.x, z3.y, z3.z, z3.w};
        float mm = 0.0f;
#pragma unroll
        for (int c = 0; c < 16; c++) mm += zv[c];
        mm *= (1.0f / 16.0f);
        float ss2 = 0.0f;
#pragma unroll
        for (int c = 0; c < 16; c++) { float d = zv[c] - mm; ss2 += d * d; }
        float inv = rsqrtf(ss2 * (1.0f / 16.0f) + 1e-5f);
        float bh0 = 0, bh1 = 0, bh2 = 0, bh3 = 0;
#pragma unroll
        for (int c = 0; c < 16; c++) {
            float zn = (zv[c] - mm) * inv * gzs[c];
            bh0 += zn * wzs[c * 4 + 0];
            bh1 += zn * wzs[c * 4 + 1];
            bh2 += zn * wzs[c * 4 + 2];
            bh3 += zn * wzs[c * 4 + 3];
        }
        biasS[0 * 4096 + p] = bh0;
        biasS[1 * 4096 + p] = bh1;
        biasS[2 * 4096 + p] = bh2;
        biasS[3 * 4096 + p] = bh3;
    }
    __syncthreads();

    int kbase = nb * NQ_ - (NK_ - NQ_) / 2;
    int warp = tid >> 5, lane = tid & 31;
    int q0 = warp * 4;

    for (int h = 0; h < H_; h++) {
        for (int e = tid; e < NK_ * DH_ / 4; e += 256) {
            int j = e >> 3;
            int d = (e & 7) * 4;
            int t = kbase + j;
            t = t < 0 ? 0 : (t >= N_ ? N_ - 1 : t);
            size_t off = ((size_t)b * N_ + t) * CA_ + h * DH_ + d;
            float4 kv = *(const float4*)(kg + off);
            Ks[j * 33 + d + 0] = kv.x; Ks[j * 33 + d + 1] = kv.y;
            Ks[j * 33 + d + 2] = kv.z; Ks[j * 33 + d + 3] = kv.w;
            float4 vv = *(const float4*)(vg + off);
            Vs[j * 33 + d + 0] = vv.x; Vs[j * 33 + d + 1] = vv.y;
            Vs[j * 33 + d + 2] = vv.z; Vs[j * 33 + d + 3] = vv.w;
        }
        __syncthreads();

        float* sc = biasS + h * (NQ_ * NK_);
        const float* qr0 = Qs + (q0 + 0) * CA_ + h * DH_;
        const float* qr1 = Qs + (q0 + 1) * CA_ + h * DH_;
        const float* qr2 = Qs + (q0 + 2) * CA_ + h * DH_;
        const float* qr3 = Qs + (q0 + 3) * CA_ + h * DH_;

#pragma unroll
        for (int ch = 0; ch < 4; ch++) {
            int kj = ch * 32 + lane;
            const float* kcol = Ks + kj * 33;
            float a0 = 0, a1v = 0, a2 = 0, a3v = 0;
#pragma unroll
            for (int d = 0; d < 32; d++) {
                float kv = kcol[d];
                a0  += qr0[d] * kv;
                a1v += qr1[d] * kv;
                a2  += qr2[d] * kv;
                a3v += qr3[d] * kv;
            }
            int t = kbase + kj;
            bool valid = (t >= 0 && t < N_);
            const float sc_ = 0.17677669529663687f;
            sc[(q0 + 0) * NK_ + kj] = valid ? a0  * sc_ + sc[(q0 + 0) * NK_ + kj] : -1e9f;
            sc[(q0 + 1) * NK_ + kj] = valid ? a1v * sc_ + sc[(q0 + 1) * NK_ + kj] : -1e9f;
            sc[(q0 + 2) * NK_ + kj] = valid ? a2  * sc_ + sc[(q0 + 2) * NK_ + kj] : -1e9f;
            sc[(q0 + 3) * NK_ + kj] = valid ? a3v * sc_ + sc[(q0 + 3) * NK_ + kj] : -1e9f;
        }
        __syncthreads();

#pragma unroll
        for (int rr = 0; rr < 4; rr++) {
            float* row = sc + (q0 + rr) * NK_;
            float v0 = row[lane], v1 = row[lane + 32], v2 = row[lane + 64], v3 = row[lane + 96];
            float mx = fmaxf(fmaxf(v0, v1), fmaxf(v2, v3));
#pragma unroll
            for (int o2 = 16; o2; o2 >>= 1) mx = fmaxf(mx, __shfl_xor_sync(0xffffffffu, mx, o2));
            v0 = __expf(v0 - mx); v1 = __expf(v1 - mx);
            v2 = __expf(v2 - mx); v3 = __expf(v3 - mx);
            float sum = v0 + v1 + v2 + v3;
#pragma unroll
            for (int o2 = 16; o2; o2 >>= 1) sum += __shfl_xor_sync(0xffffffffu, sum, o2);
            float invs = 1.0f / sum;
            row[lane]      = v0 * invs; row[lane + 32] = v1 * invs;
            row[lane + 64] = v2 * invs; row[lane + 96] = v3 * invs;
        }
        __syncthreads();

        {
            const float* p0 = sc + (q0 + 0) * NK_;
            const float* p1 = sc + (q0 + 1) * NK_;
            const float* p2 = sc + (q0 + 2) * NK_;
            const float* p3 = sc + (q0 + 3) * NK_;
            float o0 = 0, o1v = 0, o2v = 0, o3 = 0;
#pragma unroll 8
            for (int kj = 0; kj < NK_; kj++) {
                float vv = Vs[kj * 33 + lane];
                o0  += p0[kj] * vv;
                o1v += p1[kj] * vv;
                o2v += p2[kj] * vv;
                o3  += p3[kj] * vv;
            }
            size_t ob0 = ((size_t)b * N_ + nb * NQ_ + q0) * CA_ + h * DH_ + lane;
            o[ob0 + 0 * CA_] = o0;
            o[ob0 + 1 * CA_] = o1v;
            o[ob0 + 2 * CA_] = o2v;
            o[ob0 + 3 * CA_] = o3;
        }
        __syncthreads();
    }
}

// ---------------------------------------------------------------------------
// Host launch
// ---------------------------------------------------------------------------
extern "C" void kernel_launch(void* const* d_in, const int* in_sizes, int n_in,
                              void* d_out, int out_size)
{
    const float* a       = (const float*)d_in[0];
    const float* s       = (const float*)d_in[1];
    const float* z       = (const float*)d_in[2];
    const float* apb_gam = (const float*)d_in[3];
    const float* apb_Wg  = (const float*)d_in[4];
    const float* apb_bg  = (const float*)d_in[5];
    const float* apb_Wsk = (const float*)d_in[6];
    const float* Wq      = (const float*)d_in[7];
    const float* bq      = (const float*)d_in[8];
    const float* Wk      = (const float*)d_in[9];
    const float* Wv      = (const float*)d_in[10];
    const float* Wgate   = (const float*)d_in[11];
    const float* Wo      = (const float*)d_in[12];
    const float* gamma_z = (const float*)d_in[13];
    const float* Wz      = (const float*)d_in[14];
    const float* Ws_last = (const float*)d_in[15];
    const float* bs_last = (const float*)d_in[16];
    const float* ct_gam  = (const float*)d_in[17];
    const float* ct_Wg   = (const float*)d_in[18];
    const float* ct_bg   = (const float*)d_in[19];
    const float* ct_Wsk  = (const float*)d_in[20];
    const float* Wa1     = (const float*)d_in[21];
    const float* Wa2     = (const float*)d_in[22];
    const float* Wb      = (const float*)d_in[23];
    const float* Ws      = (const float*)d_in[24];
    const float* bsv     = (const float*)d_in[25];
    float* out = (float*)d_out;

    float* S = nullptr;
    cudaGetSymbolAddress((void**)&S, g_scratch);
    auto buf = [&](int i) { return S + (size_t)i * SLOT; };
    float* a_n   = buf(0);
    float* s_apb = buf(1);
    float* s_ct  = buf(2);
    float* gapb  = buf(3);
    float* kapb  = buf(4);
    float* gct   = buf(5);
    float* kct   = buf(6);
    float* glast = buf(7);
    float* sg    = buf(8);
    float* a1    = buf(9);
    float* a3    = buf(10);
    float* qb    = buf(11);
    float* kb    = buf(12);
    float* vb    = buf(13);
    float* gate  = buf(14);
    float* u1    = buf(15);  // M x 256 (slots 15-16)
    float* u2    = buf(17);  // M x 256 (slots 17-18)
    float* ctp   = buf(19);
    float* ob    = buf(20);
    float* wbase = buf(21);  // tf32 weights (< 300K floats used)
    float* s_r   = buf(22);  // own slot — fixes R3 OOB

    float* wWg   = wbase + 0;
    float* wWsk  = wbase + 16384;
    float* wcWg  = wbase + 32768;
    float* wcWsk = wbase + 49152;
    float* wWsl  = wbase + 65536;
    float* wWs   = wbase + 81920;
    float* wWq   = wbase + 98304;
    float* wWk   = wbase + 114688;
    float* wWv   = wbase + 131072;
    float* wWgt  = wbase + 147456;
    float* wWo   = wbase + 163840;
    float* wWa1  = wbase + 180224;  // 128x256
    float* wWa2  = wbase + 212992;  // 128x256
    float* wWb   = wbase + 245760;  // 256x128

    WPack wp;
    const float* wsrc[14] = {apb_Wg, apb_Wsk, ct_Wg, ct_Wsk, Ws_last, Ws, Wq, Wk, Wv,
                             Wgate, Wo, Wa1, Wa2, Wb};
    float* wdst[14] = {wWg, wWsk, wcWg, wcWsk, wWsl, wWs, wWq, wWk, wWv,
                       wWgt, wWo, wWa1, wWa2, wWb};
    int wn[14] = {16384, 16384, 16384, 16384, 16384, 16384, 16384, 16384, 16384,
                  16384, 16384, 32768, 32768, 32768};
    for (int i = 0; i < 14; i++) { wp.src[i] = wsrc[i]; wp.dst[i] = wdst[i]; wp.n[i] = wn[i]; }
    cvtw_kernel<<<dim3(16, 14), 256>>>(wp);

    ln_kernel<<<M_ / 8, 256>>>(a, s, apb_gam, ct_gam, a_n, s_apb, s_ct, s_r);

    cudaFuncSetAttribute(gemm_tc, cudaFuncAttributeMaxDynamicSharedMemorySize, GEMM_SMEM);
    cudaFuncSetAttribute(attn_kernel, cudaFuncAttributeMaxDynamicSharedMemorySize,
                         ATTN_SMEM_FLOATS * 4);

    auto zero_segs = [&]() {
        GemmSegs g{};
        for (int i = 0; i < 4; i++) {
            g.W[i] = nullptr; g.bias[i] = nullptr; g.C[i] = nullptr;
            g.e1[i] = nullptr; g.e2[i] = nullptr;
            g.ldW[i] = 128; g.ldC[i] = 128; g.ep[i] = 0;
        }
        return g;
    };

    // L1: s_apb -> sigmoid gate (fused bias) + skip
    {
        GemmSegs g = zero_segs();
        g.W[0] = wWg;  g.bias[0] = apb_bg; g.C[0] = gapb; g.ep[0] = 1;
        g.W[1] = wWsk; g.C[1] = kapb;
        gemm_tc<<<dim3(M_ / 128, 2), 256, GEMM_SMEM>>>(s_apb, nullptr, 128, 1, g);
    }
    // L2: s_ct
    {
        GemmSegs g = zero_segs();
        g.W[0] = wcWg;  g.bias[0] = ct_bg; g.C[0] = gct; g.ep[0] = 1;
        g.W[1] = wcWsk; g.C[1] = kct;
        gemm_tc<<<dim3(M_ / 128, 2), 256, GEMM_SMEM>>>(s_ct, nullptr, 128, 1, g);
    }
    // L3: s -> glast, sg (sigmoid + bias fused)
    {
        GemmSegs g = zero_segs();
        g.W[0] = wWsl; g.bias[0] = bs_last; g.C[0] = glast; g.ep[0] = 1;
        g.W[1] = wWs;  g.bias[1] = bsv;     g.C[1] = sg;    g.ep[1] = 1;
        gemm_tc<<<dim3(M_ / 128, 2), 256, GEMM_SMEM>>>(s_r, nullptr, 128, 1, g);
    }

    combine1_kernel<<<(int)(SLOT / 4 / 256), 256>>>(gapb, kapb, gct, kct, a_n, a1, a3);

    // L4: a1 -> q,k,v,gate
    {
        GemmSegs g = zero_segs();
        g.W[0] = wWq;  g.bias[0] = bq; g.C[0] = qb;
        g.W[1] = wWk;  g.C[1] = kb;
        g.W[2] = wWv;  g.C[2] = vb;
        g.W[3] = wWgt; g.C[3] = gate; g.ep[3] = 1;
        gemm_tc<<<dim3(M_ / 128, 4), 256, GEMM_SMEM>>>(a1, nullptr, 128, 1, g);
    }
    // L5: a3 -> u1, u2 (N=256 each, split into 128-col segments)
    {
        GemmSegs g = zero_segs();
        g.W[0] = wWa1;       g.C[0] = u1;       g.ldW[0] = 256; g.ldC[0] = 256;
        g.W[1] = wWa1 + 128; g.C[1] = u1 + 128; g.ldW[1] = 256; g.ldC[1] = 256;
        g.W[2] = wWa2;       g.C[2] = u2;       g.ldW[2] = 256; g.ldC[2] = 256;
        g.W[3] = wWa2 + 128; g.C[3] = u2 + 128; g.ldW[3] = 256; g.ldC[3] = 256;
        gemm_tc<<<dim3(M_ / 128, 4), 256, GEMM_SMEM>>>(a3, nullptr, 128, 1, g);
    }

    silu_kernel<<<(int)(2 * SLOT / 4 / 256), 256>>>(u1, u2);

    // L6: ct_out = sg * (t @ Wb), K=256
    {
        GemmSegs g = zero_segs();
        g.W[0] = wWb; g.C[0] = ctp; g.ep[0] = 2; g.e1[0] = sg;
        gemm_tc<<<dim3(M_ / 128, 1), 256, GEMM_SMEM>>>(u1, nullptr, 256, 1, g);
    }

    attn_kernel<<<dim3(NB_, B_), 256, ATTN_SMEM_FLOATS * 4>>>(qb, kb, vb, z, gamma_z, Wz, ob);

    // L7: out = glast * ((gate*o) @ Wo) + ctp   (ldg path: elementwise premultiply)
    {
        GemmSegs g = zero_segs();
        g.W[0] = wWo; g.C[0] = out; g.ep[0] = 3; g.e1[0] = glast; g.e2[0] = ctp;
        gemm_tc<<<dim3(M_ / 128, 1), 256, GEMM_SMEM>>>(ob, gate, 128, 0, g);
    }
}

// round 5
// speedup vs baseline: 2.3752x; 1.1382x over previous
#include <cuda_runtime.h>
#include <cuda_fp16.h>
#include <cstdint>

// ---------------------------------------------------------------------------
// AtomAttentionEncoder fused pipeline (round 5: fp16 HMMA GEMMs, batched segs)
// B=2, N=16384, CA=CS=128, CZ=16, H=4, NQ=32, NK=128, DH=32, NB=512
// ---------------------------------------------------------------------------

constexpr int B_  = 2;
constexpr int N_  = 16384;
constexpr int CA_ = 128;
constexpr int CZ_ = 16;
constexpr int H_  = 4;
constexpr int NQ_ = 32;
constexpr int NK_ = 128;
constexpr int DH_ = 32;
constexpr int NB_ = 512;

constexpr int    M_   = B_ * N_;               // 32768 tokens
constexpr size_t SLOT = (size_t)M_ * CA_;      // 4,194,304 floats

__device__ float g_scratch[23 * SLOT];

__device__ __forceinline__ float sigmoidf_(float x) { return 1.0f / (1.0f + __expf(-x)); }

#define MMA_F16(cc, aa, bb)                                                    \
    asm volatile("mma.sync.aligned.m16n8k16.row.col.f32.f16.f16.f32 "          \
                 "{%0,%1,%2,%3}, {%4,%5,%6,%7}, {%8,%9}, {%0,%1,%2,%3};"       \
                 : "+f"(cc[0]), "+f"(cc[1]), "+f"(cc[2]), "+f"(cc[3])          \
                 : "r"(aa[0]), "r"(aa[1]), "r"(aa[2]), "r"(aa[3]),             \
                   "r"(bb[0]), "r"(bb[1]))

__device__ __forceinline__ void cp_async16(uint32_t smem_addr, const void* gptr) {
    asm volatile("cp.async.cg.shared.global [%0], [%1], 16;\n"
                 :: "r"(smem_addr), "l"(gptr));
}
__device__ __forceinline__ void cp_commit() { asm volatile("cp.async.commit_group;\n"); }
__device__ __forceinline__ void cp_wait1()  { asm volatile("cp.async.wait_group 1;\n"); }

// ---------------------------------------------------------------------------
// Weight conversion: Wt[n*K + k] = half(W[k*N + n])   (transpose + fp16)
// ---------------------------------------------------------------------------
struct WtPack {
    const float* src[14];
    __half*      dst[14];
    int          K[14];
    int          N[14];
};
__global__ void cvtw_kernel(WtPack p)
{
    int y = blockIdx.y;
    int K = p.K[y], N = p.N[y];
    const float* s = p.src[y];
    __half* d = p.dst[y];
    int total = K * N;
    for (int i = blockIdx.x * 256 + threadIdx.x; i < total; i += gridDim.x * 256) {
        int k = i / N, n = i % N;
        d[n * K + k] = __float2half(s[i]);
    }
}

// ---------------------------------------------------------------------------
// LayerNorm: a_n = LN(a) fp32; s_apbh = h(LN(s)*g_apb); s_cth = h(LN(s)*g_ct);
// s_rh = h(s)
// ---------------------------------------------------------------------------
__global__ void ln_kernel(const float* __restrict__ a, const float* __restrict__ s,
                          const float* __restrict__ apbg, const float* __restrict__ ctg,
                          float* __restrict__ a_n, __half* __restrict__ s_apbh,
                          __half* __restrict__ s_cth, __half* __restrict__ s_rh)
{
    int warp = (blockIdx.x * blockDim.x + threadIdx.x) >> 5;
    int lane = threadIdx.x & 31;
    if (warp >= M_) return;
    size_t base = (size_t)warp * CA_;

    float4 av = ((const float4*)(a + base))[lane];
    float sum = av.x + av.y + av.z + av.w;
    float sq  = av.x * av.x + av.y * av.y + av.z * av.z + av.w * av.w;
#pragma unroll
    for (int o = 16; o; o >>= 1) {
        sum += __shfl_xor_sync(0xffffffffu, sum, o);
        sq  += __shfl_xor_sync(0xffffffffu, sq,  o);
    }
    float m   = sum * (1.0f / 128.0f);
    float inv = rsqrtf(sq * (1.0f / 128.0f) - m * m + 1e-5f);
    float4 ao;
    ao.x = (av.x - m) * inv; ao.y = (av.y - m) * inv;
    ao.z = (av.z - m) * inv; ao.w = (av.w - m) * inv;
    ((float4*)(a_n + base))[lane] = ao;

    float4 sv = ((const float4*)(s + base))[lane];
    {
        __half* p = s_rh + base + lane * 4;
        *(__half2*)(p)     = __floats2half2_rn(sv.x, sv.y);
        *(__half2*)(p + 2) = __floats2half2_rn(sv.z, sv.w);
    }

    float sums = sv.x + sv.y + sv.z + sv.w;
    float sqs  = sv.x * sv.x + sv.y * sv.y + sv.z * sv.z + sv.w * sv.w;
#pragma unroll
    for (int o = 16; o; o >>= 1) {
        sums += __shfl_xor_sync(0xffffffffu, sums, o);
        sqs  += __shfl_xor_sync(0xffffffffu, sqs,  o);
    }
    float ms   = sums * (1.0f / 128.0f);
    float invs = rsqrtf(sqs * (1.0f / 128.0f) - ms * ms + 1e-5f);
    float4 sn;
    sn.x = (sv.x - ms) * invs; sn.y = (sv.y - ms) * invs;
    sn.z = (sv.z - ms) * invs; sn.w = (sv.w - ms) * invs;

    float4 g1 = ((const float4*)apbg)[lane];
    float4 g2 = ((const float4*)ctg)[lane];
    {
        __half* p = s_apbh + base + lane * 4;
        *(__half2*)(p)     = __floats2half2_rn(sn.x * g1.x, sn.y * g1.y);
        *(__half2*)(p + 2) = __floats2half2_rn(sn.z * g1.z, sn.w * g1.w);
    }
    {
        __half* p = s_cth + base + lane * 4;
        *(__half2*)(p)     = __floats2half2_rn(sn.x * g2.x, sn.y * g2.y);
        *(__half2*)(p + 2) = __floats2half2_rn(sn.z * g2.z, sn.w * g2.w);
    }
}

// ---------------------------------------------------------------------------
// Multi-segment fp16 GEMM: C[M,128] = epilogue( A[M,K] @ Wt[128,K]^T + bias )
// A half (cp.async, mode 0) or fused silu(u1)*u2 from fp32 (mode 1).
// Wt pre-transposed [N][K] half. ep: 0 none, 1 sigmoid, 2 e1*acc, 3 e1*acc+e2
// Tile 128x128, BK=64, 8 warps (2x4), m16n8k16. 2 stages cp.async.
// ---------------------------------------------------------------------------
struct Seg {
    const __half* A;
    const __half* Wt;
    const float*  bias;
    float*        C;
    const float*  e1;
    const float*  e2;
    int           ldC;
    int           ep;
};
struct GemmArgs { Seg seg[8]; };

constexpr int HST = 128 * 72;                 // halves per stage (stride 72)
constexpr int GEMM_SMEM = 4 * HST * 2;        // bytes = 73728

__global__ void __launch_bounds__(256, 2) gemm_h(
    int K, int mode, const float* __restrict__ U1, const float* __restrict__ U2,
    GemmArgs args)
{
    extern __shared__ __half smh[];
    int tid  = threadIdx.x;
    int warp = tid >> 5, lane = tid & 31;
    int wm = (warp >> 2) * 64;
    int wn = (warp & 3) * 32;
    int gid = lane >> 2, qid = lane & 3;
    int row0 = blockIdx.x * 128;
    int y = blockIdx.y;
    const __half* Aseg = args.seg[y].A;
    const __half* Wt   = args.seg[y].Wt;
    int KT = K >> 6;

    uint32_t smBase;
    asm("{ .reg .u64 t; cvta.to.shared.u64 t, %1; cvt.u32.u64 %0, t; }"
        : "=r"(smBase) : "l"(smh));

    auto loadA = [&](int kt, int st) {
        if (mode == 0) {
#pragma unroll
            for (int i = 0; i < 4; i++) {
                int e  = tid + i * 256;
                int r  = e >> 3;
                int c8 = (e & 7) * 8;
                uint32_t dst = smBase + (uint32_t)(st * HST + r * 72 + c8) * 2u;
                cp_async16(dst, Aseg + (size_t)(row0 + r) * K + kt * 64 + c8);
            }
        } else {
            __half* As = smh + st * HST;
#pragma unroll
            for (int i = 0; i < 8; i++) {
                int e  = tid + i * 256;
                int r  = e >> 4;
                int c4 = (e & 15) * 4;
                size_t off = (size_t)(row0 + r) * K + kt * 64 + c4;
                float4 x = *(const float4*)(U1 + off);
                float4 w = *(const float4*)(U2 + off);
                float t0 = x.x * sigmoidf_(x.x) * w.x;
                float t1 = x.y * sigmoidf_(x.y) * w.y;
                float t2 = x.z * sigmoidf_(x.z) * w.z;
                float t3 = x.w * sigmoidf_(x.w) * w.w;
                __half* p = As + r * 72 + c4;
                *(__half2*)(p)     = __floats2half2_rn(t0, t1);
                *(__half2*)(p + 2) = __floats2half2_rn(t2, t3);
            }
        }
    };
    auto loadB = [&](int kt, int st) {
#pragma unroll
        for (int i = 0; i < 4; i++) {
            int e  = tid + i * 256;
            int n  = e >> 3;
            int c8 = (e & 7) * 8;
            uint32_t dst = smBase + (uint32_t)(2 * HST + st * HST + n * 72 + c8) * 2u;
            cp_async16(dst, Wt + (size_t)n * K + kt * 64 + c8);
        }
    };

    float c[4][4][4];
#pragma unroll
    for (int mi = 0; mi < 4; mi++)
#pragma unroll
        for (int ni = 0; ni < 4; ni++)
#pragma unroll
            for (int r = 0; r < 4; r++) c[mi][ni][r] = 0.0f;

    loadA(0, 0); loadB(0, 0); cp_commit();
    if (KT > 1) { loadA(1, 1); loadB(1, 1); cp_commit(); }

    for (int kt = 0; kt < KT; kt++) {
        cp_wait1();
        __syncthreads();
        int st = kt & 1;
        const __half* As = smh + st * HST;
        const __half* Bs = smh + 2 * HST + st * HST;
#pragma unroll
        for (int ks = 0; ks < 4; ks++) {
            int kb = ks * 16;
            uint32_t af[4][4], bf[4][2];
#pragma unroll
            for (int mi = 0; mi < 4; mi++) {
                int ra = (wm + mi * 16 + gid) * 72 + kb + 2 * qid;
                af[mi][0] = *(const uint32_t*)(As + ra);
                af[mi][1] = *(const uint32_t*)(As + ra + 8 * 72);
                af[mi][2] = *(const uint32_t*)(As + ra + 8);
                af[mi][3] = *(const uint32_t*)(As + ra + 8 * 72 + 8);
            }
#pragma unroll
            for (int ni = 0; ni < 4; ni++) {
                int rb = (wn + ni * 8 + gid) * 72 + kb + 2 * qid;
                bf[ni][0] = *(const uint32_t*)(Bs + rb);
                bf[ni][1] = *(const uint32_t*)(Bs + rb + 8);
            }
#pragma unroll
            for (int mi = 0; mi < 4; mi++)
#pragma unroll
                for (int ni = 0; ni < 4; ni++)
                    MMA_F16(c[mi][ni], af[mi], bf[ni]);
        }
        __syncthreads();
        if (kt + 2 < KT) { loadA(kt + 2, st); loadB(kt + 2, st); }
        cp_commit();
    }

    const float* bias = args.seg[y].bias;
    float* C = args.seg[y].C;
    const float* e1 = args.seg[y].e1;
    const float* e2 = args.seg[y].e2;
    int ldC = args.seg[y].ldC;
    int ep  = args.seg[y].ep;

#pragma unroll
    for (int mi = 0; mi < 4; mi++) {
#pragma unroll
        for (int ni = 0; ni < 4; ni++) {
            int rA = row0 + wm + mi * 16 + gid;
            int cc = wn + ni * 8 + qid * 2;
            float b0 = bias ? bias[cc]     : 0.0f;
            float b1 = bias ? bias[cc + 1] : 0.0f;
#pragma unroll
            for (int h = 0; h < 2; h++) {
                size_t idx = (size_t)(rA + h * 8) * ldC + cc;
                float v0 = c[mi][ni][h * 2 + 0] + b0;
                float v1 = c[mi][ni][h * 2 + 1] + b1;
                if (ep == 1)      { v0 = sigmoidf_(v0); v1 = sigmoidf_(v1); }
                else if (ep == 2) { v0 *= e1[idx]; v1 *= e1[idx + 1]; }
                else if (ep == 3) { v0 = e1[idx] * v0 + e2[idx];
                                    v1 = e1[idx + 1] * v1 + e2[idx + 1]; }
                *(float2*)(C + idx) = make_float2(v0, v1);
            }
        }
    }
}

// ---------------------------------------------------------------------------
// Combine: a1h = h(gapb*a_n + kapb); a3h = h(gct*a_n + kct)
// ---------------------------------------------------------------------------
__global__ void combine1_kernel(
    const float* __restrict__ gapb, const float* __restrict__ kapb,
    const float* __restrict__ gct,  const float* __restrict__ kct,
    const float* __restrict__ a_n,
    __half* __restrict__ a1h, __half* __restrict__ a3h)
{
    size_t i = (size_t)blockIdx.x * blockDim.x + threadIdx.x;
    float4 van = ((const float4*)a_n)[i];
    float4 v1, v2;

    v1 = ((const float4*)gapb)[i];
    v2 = ((const float4*)kapb)[i];
    {
        __half* p = a1h + i * 4;
        *(__half2*)(p)     = __floats2half2_rn(v1.x * van.x + v2.x, v1.y * van.y + v2.y);
        *(__half2*)(p + 2) = __floats2half2_rn(v1.z * van.z + v2.z, v1.w * van.w + v2.w);
    }

    v1 = ((const float4*)gct)[i];
    v2 = ((const float4*)kct)[i];
    {
        __half* p = a3h + i * 4;
        *(__half2*)(p)     = __floats2half2_rn(v1.x * van.x + v2.x, v1.y * van.y + v2.y);
        *(__half2*)(p + 2) = __floats2half2_rn(v1.z * van.z + v2.z, v1.w * van.w + v2.w);
    }
}

// ---------------------------------------------------------------------------
// Fused local attention. Writes obh = half(gate * attn_out).
// ---------------------------------------------------------------------------
constexpr int ATTN_SMEM_FLOATS = H_ * NQ_ * NK_ + NQ_ * CA_ + 2 * NK_ * 33;  // 28928

__global__ void __launch_bounds__(256) attn_kernel(
    const float* __restrict__ q, const float* __restrict__ kg,
    const float* __restrict__ vg, const float* __restrict__ z,
    const float* __restrict__ gamma_z, const float* __restrict__ Wz,
    const float* __restrict__ gate, __half* __restrict__ obh)
{
    extern __shared__ float sm[];
    float* biasS = sm;
    float* Qs = biasS + H_ * NQ_ * NK_;
    float* Ks = Qs + NQ_ * CA_;
    float* Vs = Ks + NK_ * 33;
    __shared__ float gzs[CZ_];
    __shared__ float wzs[CZ_ * H_];

    int tid = threadIdx.x;
    int nb = blockIdx.x, b = blockIdx.y;
    if (tid < CZ_)      gzs[tid] = gamma_z[tid];
    if (tid < CZ_ * H_) wzs[tid] = Wz[tid];

    for (int e = tid; e < NQ_ * CA_ / 4; e += 256) {
        int qq = e >> 5;
        int c  = (e & 31) * 4;
        ((float4*)Qs)[e] = *(const float4*)(q + ((size_t)b * N_ + nb * NQ_ + qq) * CA_ + c);
    }
    __syncthreads();

    const float* zb = z + ((size_t)(b * NB_ + nb)) * NQ_ * NK_ * CZ_;
#pragma unroll 1
    for (int i = 0; i < 16; i++) {
        int p = tid + i * 256;
        const float4* zp = (const float4*)(zb + (size_t)p * CZ_);
        float4 z0 = zp[0], z1 = zp[1], z2 = zp[2], z3 = zp[3];
        float zv[16] = {z0.x, z0.y, z0.z, z0.w, z1.x, z1.y, z1.z, z1.w,
                        z2.x, z2.y, z2.z, z2.w, z3.x, z3.y, z3.z, z3.w};
        float mm = 0.0f;
#pragma unroll
        for (int c = 0; c < 16; c++) mm += zv[c];
        mm *= (1.0f / 16.0f);
        float ss2 = 0.0f;
#pragma unroll
        for (int c = 0; c < 16; c++) { float d = zv[c] - mm; ss2 += d * d; }
        float inv = rsqrtf(ss2 * (1.0f / 16.0f) + 1e-5f);
        float bh0 = 0, bh1 = 0, bh2 = 0, bh3 = 0;
#pragma unroll
        for (int c = 0; c < 16; c++) {
            float zn = (zv[c] - mm) * inv * gzs[c];
            bh0 += zn * wzs[c * 4 + 0];
            bh1 += zn * wzs[c * 4 + 1];
            bh2 += zn * wzs[c * 4 + 2];
            bh3 += zn * wzs[c * 4 + 3];
        }
        biasS[0 * 4096 + p] = bh0;
        biasS[1 * 4096 + p] = bh1;
        biasS[2 * 4096 + p] = bh2;
        biasS[3 * 4096 + p] = bh3;
    }
    __syncthreads();

    int kbase = nb * NQ_ - (NK_ - NQ_) / 2;
    int warp = tid >> 5, lane = tid & 31;
    int q0 = warp * 4;

    for (int h = 0; h < H_; h++) {
        for (int e = tid; e < NK_ * DH_ / 4; e += 256) {
            int j = e >> 3;
            int d = (e & 7) * 4;
            int t = kbase + j;
            t = t < 0 ? 0 : (t >= N_ ? N_ - 1 : t);
            size_t off = ((size_t)b * N_ + t) * CA_ + h * DH_ + d;
            float4 kv = *(const float4*)(kg + off);
            Ks[j * 33 + d + 0] = kv.x; Ks[j * 33 + d + 1] = kv.y;
            Ks[j * 33 + d + 2] = kv.z; Ks[j * 33 + d + 3] = kv.w;
            float4 vv = *(const float4*)(vg + off);
            Vs[j * 33 + d + 0] = vv.x; Vs[j * 33 + d + 1] = vv.y;
            Vs[j * 33 + d + 2] = vv.z; Vs[j * 33 + d + 3] = vv.w;
        }
        __syncthreads();

        float* sc = biasS + h * (NQ_ * NK_);
        const float* qr0 = Qs + (q0 + 0) * CA_ + h * DH_;
        const float* qr1 = Qs + (q0 + 1) * CA_ + h * DH_;
        const float* qr2 = Qs + (q0 + 2) * CA_ + h * DH_;
        const float* qr3 = Qs + (q0 + 3) * CA_ + h * DH_;

#pragma unroll
        for (int ch = 0; ch < 4; ch++) {
            int kj = ch * 32 + lane;
            const float* kcol = Ks + kj * 33;
            float a0 = 0, a1v = 0, a2 = 0, a3v = 0;
#pragma unroll
            for (int d = 0; d < 32; d++) {
                float kv = kcol[d];
                a0  += qr0[d] * kv;
                a1v += qr1[d] * kv;
                a2  += qr2[d] * kv;
                a3v += qr3[d] * kv;
            }
            int t = kbase + kj;
            bool valid = (t >= 0 && t < N_);
            const float sc_ = 0.17677669529663687f;
            sc[(q0 + 0) * NK_ + kj] = valid ? a0  * sc_ + sc[(q0 + 0) * NK_ + kj] : -1e9f;
            sc[(q0 + 1) * NK_ + kj] = valid ? a1v * sc_ + sc[(q0 + 1) * NK_ + kj] : -1e9f;
            sc[(q0 + 2) * NK_ + kj] = valid ? a2  * sc_ + sc[(q0 + 2) * NK_ + kj] : -1e9f;
            sc[(q0 + 3) * NK_ + kj] = valid ? a3v * sc_ + sc[(q0 + 3) * NK_ + kj] : -1e9f;
        }
        __syncthreads();

#pragma unroll
        for (int rr = 0; rr < 4; rr++) {
            float* row = sc + (q0 + rr) * NK_;
            float v0 = row[lane], v1 = row[lane + 32], v2 = row[lane + 64], v3 = row[lane + 96];
            float mx = fmaxf(fmaxf(v0, v1), fmaxf(v2, v3));
#pragma unroll
            for (int o2 = 16; o2; o2 >>= 1) mx = fmaxf(mx, __shfl_xor_sync(0xffffffffu, mx, o2));
            v0 = __expf(v0 - mx); v1 = __expf(v1 - mx);
            v2 = __expf(v2 - mx); v3 = __expf(v3 - mx);
            float sum = v0 + v1 + v2 + v3;
#pragma unroll
            for (int o2 = 16; o2; o2 >>= 1) sum += __shfl_xor_sync(0xffffffffu, sum, o2);
            float invs = 1.0f / sum;
            row[lane]      = v0 * invs; row[lane + 32] = v1 * invs;
            row[lane + 64] = v2 * invs; row[lane + 96] = v3 * invs;
        }
        __syncthreads();

        {
            const float* p0 = sc + (q0 + 0) * NK_;
            const float* p1 = sc + (q0 + 1) * NK_;
            const float* p2 = sc + (q0 + 2) * NK_;
            const float* p3 = sc + (q0 + 3) * NK_;
            float o0 = 0, o1v = 0, o2v = 0, o3 = 0;
#pragma unroll 8
            for (int kj = 0; kj < NK_; kj++) {
                float vv = Vs[kj * 33 + lane];
                o0  += p0[kj] * vv;
                o1v += p1[kj] * vv;
                o2v += p2[kj] * vv;
                o3  += p3[kj] * vv;
            }
            size_t ob0 = ((size_t)b * N_ + nb * NQ_ + q0) * CA_ + h * DH_ + lane;
            obh[ob0 + 0 * CA_] = __float2half(gate[ob0 + 0 * CA_] * o0);
            obh[ob0 + 1 * CA_] = __float2half(gate[ob0 + 1 * CA_] * o1v);
            obh[ob0 + 2 * CA_] = __float2half(gate[ob0 + 2 * CA_] * o2v);
            obh[ob0 + 3 * CA_] = __float2half(gate[ob0 + 3 * CA_] * o3);
        }
        __syncthreads();
    }
}

// ---------------------------------------------------------------------------
// Host launch
// ---------------------------------------------------------------------------
extern "C" void kernel_launch(void* const* d_in, const int* in_sizes, int n_in,
                              void* d_out, int out_size)
{
    const float* a       = (const float*)d_in[0];
    const float* s       = (const float*)d_in[1];
    const float* z       = (const float*)d_in[2];
    const float* apb_gam = (const float*)d_in[3];
    const float* apb_Wg  = (const float*)d_in[4];
    const float* apb_bg  = (const float*)d_in[5];
    const float* apb_Wsk = (const float*)d_in[6];
    const float* Wq      = (const float*)d_in[7];
    const float* bq      = (const float*)d_in[8];
    const float* Wk      = (const float*)d_in[9];
    const float* Wv      = (const float*)d_in[10];
    const float* Wgate   = (const float*)d_in[11];
    const float* Wo      = (const float*)d_in[12];
    const float* gamma_z = (const float*)d_in[13];
    const float* Wz      = (const float*)d_in[14];
    const float* Ws_last = (const float*)d_in[15];
    const float* bs_last = (const float*)d_in[16];
    const float* ct_gam  = (const float*)d_in[17];
    const float* ct_Wg   = (const float*)d_in[18];
    const float* ct_bg   = (const float*)d_in[19];
    const float* ct_Wsk  = (const float*)d_in[20];
    const float* Wa1     = (const float*)d_in[21];
    const float* Wa2     = (const float*)d_in[22];
    const float* Wb      = (const float*)d_in[23];
    const float* Ws      = (const float*)d_in[24];
    const float* bsv     = (const float*)d_in[25];
    float* out = (float*)d_out;

    float* S = nullptr;
    cudaGetSymbolAddress((void**)&S, g_scratch);
    auto buf = [&](int i) { return S + (size_t)i * SLOT; };
    // fp32 buffers
    float* a_n   = buf(0);
    float* gapb  = buf(1);
    float* kapb  = buf(2);
    float* gct   = buf(3);
    float* kct   = buf(4);
    float* glast = buf(5);
    float* sg    = buf(6);
    float* qb    = buf(7);
    float* kb    = buf(8);
    float* vb    = buf(9);
    float* gate  = buf(10);
    float* u1    = buf(11);  // M x 256 (slots 11-12)
    float* u2    = buf(13);  // M x 256 (slots 13-14)
    float* ctp   = buf(15);
    // half buffers (each M*128 halves = SLOT halves = half a float slot)
    __half* hb     = (__half*)buf(16);
    __half* s_apbh = hb + 0 * SLOT;
    __half* s_cth  = hb + 1 * SLOT;
    __half* s_rh   = hb + 2 * SLOT;
    __half* a1h    = hb + 3 * SLOT;
    __half* a3h    = hb + 4 * SLOT;
    __half* obh    = hb + 5 * SLOT;   // ends inside slot 18
    // half weights (transposed [N][K])
    __half* wh = (__half*)buf(19);
    __half* wWg   = wh + 0;
    __half* wWsk  = wh + 16384;
    __half* wcWg  = wh + 32768;
    __half* wcWsk = wh + 49152;
    __half* wWsl  = wh + 65536;
    __half* wWs   = wh + 81920;
    __half* wWq   = wh + 98304;
    __half* wWk   = wh + 114688;
    __half* wWv   = wh + 131072;
    __half* wWgt  = wh + 147456;
    __half* wWo   = wh + 163840;
    __half* wWa1  = wh + 180224;  // [256][128]
    __half* wWa2  = wh + 212992;  // [256][128]
    __half* wWb   = wh + 245760;  // [128][256]

    WtPack wp;
    const float* wsrc[14] = {apb_Wg, apb_Wsk, ct_Wg, ct_Wsk, Ws_last, Ws, Wq, Wk, Wv,
                             Wgate, Wo, Wa1, Wa2, Wb};
    __half* wdst[14] = {wWg, wWsk, wcWg, wcWsk, wWsl, wWs, wWq, wWk, wWv,
                        wWgt, wWo, wWa1, wWa2, wWb};
    int wK[14] = {128,128,128,128,128,128,128,128,128,128,128,128,128,256};
    int wN[14] = {128,128,128,128,128,128,128,128,128,128,128,256,256,128};
    for (int i = 0; i < 14; i++) { wp.src[i] = wsrc[i]; wp.dst[i] = wdst[i];
                                   wp.K[i] = wK[i]; wp.N[i] = wN[i]; }
    cvtw_kernel<<<dim3(16, 14), 256>>>(wp);

    ln_kernel<<<M_ / 8, 256>>>(a, s, apb_gam, ct_gam, a_n, s_apbh, s_cth, s_rh);

    cudaFuncSetAttribute(gemm_h, cudaFuncAttributeMaxDynamicSharedMemorySize, GEMM_SMEM);
    cudaFuncSetAttribute(attn_kernel, cudaFuncAttributeMaxDynamicSharedMemorySize,
                         ATTN_SMEM_FLOATS * 4);

    auto mkseg = [&](const __half* A, const __half* Wt, const float* bias, float* C,
                     int ep, const float* e1, const float* e2, int ldC) {
        Seg sgm; sgm.A = A; sgm.Wt = Wt; sgm.bias = bias; sgm.C = C;
        sgm.e1 = e1; sgm.e2 = e2; sgm.ldC = ldC; sgm.ep = ep; return sgm;
    };

    // G1: 6 independent segments from the three s-derived activations
    {
        GemmArgs g{};
        g.seg[0] = mkseg(s_apbh, wWg,   apb_bg,  gapb,  1, nullptr, nullptr, 128);
        g.seg[1] = mkseg(s_apbh, wWsk,  nullptr, kapb,  0, nullptr, nullptr, 128);
        g.seg[2] = mkseg(s_cth,  wcWg,  ct_bg,   gct,   1, nullptr, nullptr, 128);
        g.seg[3] = mkseg(s_cth,  wcWsk, nullptr, kct,   0, nullptr, nullptr, 128);
        g.seg[4] = mkseg(s_rh,   wWsl,  bs_last, glast, 1, nullptr, nullptr, 128);
        g.seg[5] = mkseg(s_rh,   wWs,   bsv,     sg,    1, nullptr, nullptr, 128);
        gemm_h<<<dim3(M_ / 128, 6), 256, GEMM_SMEM>>>(128, 0, nullptr, nullptr, g);
    }

    combine1_kernel<<<(int)(SLOT / 4 / 256), 256>>>(gapb, kapb, gct, kct, a_n, a1h, a3h);

    // G2: 8 segments — qkv/gate from a1h, transition u1/u2 from a3h
    {
        GemmArgs g{};
        g.seg[0] = mkseg(a1h, wWq,          bq,      qb,       0, nullptr, nullptr, 128);
        g.seg[1] = mkseg(a1h, wWk,          nullptr, kb,       0, nullptr, nullptr, 128);
        g.seg[2] = mkseg(a1h, wWv,          nullptr, vb,       0, nullptr, nullptr, 128);
        g.seg[3] = mkseg(a1h, wWgt,         nullptr, gate,     1, nullptr, nullptr, 128);
        g.seg[4] = mkseg(a3h, wWa1,         nullptr, u1,       0, nullptr, nullptr, 256);
        g.seg[5] = mkseg(a3h, wWa1 + 16384, nullptr, u1 + 128, 0, nullptr, nullptr, 256);
        g.seg[6] = mkseg(a3h, wWa2,         nullptr, u2,       0, nullptr, nullptr, 256);
        g.seg[7] = mkseg(a3h, wWa2 + 16384, nullptr, u2 + 128, 0, nullptr, nullptr, 256);
        gemm_h<<<dim3(M_ / 128, 8), 256, GEMM_SMEM>>>(128, 0, nullptr, nullptr, g);
    }

    // G3: ct_out = sg * (silu(u1)*u2 @ Wb), K=256, silu fused into A-loader
    {
        GemmArgs g{};
        g.seg[0] = mkseg(nullptr, wWb, nullptr, ctp, 2, sg, nullptr, 128);
        gemm_h<<<dim3(M_ / 128, 1), 256, GEMM_SMEM>>>(256, 1, u1, u2, g);
    }

    // attention (bias + softmax + PV + gate multiply, half out)
    attn_kernel<<<dim3(NB_, B_), 256, ATTN_SMEM_FLOATS * 4>>>(
        qb, kb, vb, z, gamma_z, Wz, gate, obh);

    // G4: out = glast * (obh @ Wo) + ctp
    {
        GemmArgs g{};
        g.seg[0] = mkseg(obh, wWo, nullptr, out, 3, glast, ctp, 128);
        gemm_h<<<dim3(M_ / 128, 1), 256, GEMM_SMEM>>>(128, 0, nullptr, nullptr, g);
    }
}

// round 8
// speedup vs baseline: 3.1740x; 1.3363x over previous
#include <cuda_runtime.h>
#include <cuda_fp16.h>
#include <cstdint>

// ---------------------------------------------------------------------------
// AtomAttentionEncoder fused pipeline (round 6: tensor-core attention,
// fp16 intermediates end-to-end, fp32 softmax/bias/epilogues)
// B=2, N=16384, CA=CS=128, CZ=16, H=4, NQ=32, NK=128, DH=32, NB=512
// ---------------------------------------------------------------------------

constexpr int B_  = 2;
constexpr int N_  = 16384;
constexpr int CA_ = 128;
constexpr int CZ_ = 16;
constexpr int H_  = 4;
constexpr int NB_ = 512;

constexpr int    M_   = B_ * N_;               // 32768 tokens
constexpr size_t SLOT = (size_t)M_ * CA_;      // 4,194,304 floats

__device__ float g_scratch[13 * SLOT];

__device__ __forceinline__ float sigmoidf_(float x) { return 1.0f / (1.0f + __expf(-x)); }

#define MMA_F16(cc, aa, bb)                                                    \
    asm volatile("mma.sync.aligned.m16n8k16.row.col.f32.f16.f16.f32 "          \
                 "{%0,%1,%2,%3}, {%4,%5,%6,%7}, {%8,%9}, {%0,%1,%2,%3};"       \
                 : "+f"(cc[0]), "+f"(cc[1]), "+f"(cc[2]), "+f"(cc[3])          \
                 : "r"(aa[0]), "r"(aa[1]), "r"(aa[2]), "r"(aa[3]),             \
                   "r"(bb[0]), "r"(bb[1]))

__device__ __forceinline__ void cp_async16(uint32_t smem_addr, const void* gptr) {
    asm volatile("cp.async.cg.shared.global [%0], [%1], 16;\n"
                 :: "r"(smem_addr), "l"(gptr));
}
__device__ __forceinline__ void cp_commit() { asm volatile("cp.async.commit_group;\n"); }
__device__ __forceinline__ void cp_wait1()  { asm volatile("cp.async.wait_group 1;\n"); }

__device__ __forceinline__ uint32_t smem_u32(const void* p) {
    uint32_t a;
    asm("{ .reg .u64 t; cvta.to.shared.u64 t, %1; cvt.u32.u64 %0, t; }" : "=r"(a) : "l"(p));
    return a;
}

// ---------------------------------------------------------------------------
// Weight conversion: Wt[n*K + k] = half(W[k*N + n])
// ---------------------------------------------------------------------------
struct WtPack {
    const float* src[14];
    __half*      dst[14];
    int          K[14];
    int          N[14];
};
__global__ void cvtw_kernel(WtPack p)
{
    int y = blockIdx.y;
    int K = p.K[y], N = p.N[y];
    const float* s = p.src[y];
    __half* d = p.dst[y];
    int total = K * N;
    for (int i = blockIdx.x * 256 + threadIdx.x; i < total; i += gridDim.x * 256) {
        int k = i / N, n = i % N;
        d[n * K + k] = __float2half(s[i]);
    }
}

// ---------------------------------------------------------------------------
// LayerNorm
// ---------------------------------------------------------------------------
__global__ void ln_kernel(const float* __restrict__ a, const float* __restrict__ s,
                          const float* __restrict__ apbg, const float* __restrict__ ctg,
                          float* __restrict__ a_n, __half* __restrict__ s_apbh,
                          __half* __restrict__ s_cth, __half* __restrict__ s_rh)
{
    int warp = (blockIdx.x * blockDim.x + threadIdx.x) >> 5;
    int lane = threadIdx.x & 31;
    if (warp >= M_) return;
    size_t base = (size_t)warp * CA_;

    float4 av = ((const float4*)(a + base))[lane];
    float sum = av.x + av.y + av.z + av.w;
    float sq  = av.x * av.x + av.y * av.y + av.z * av.z + av.w * av.w;
#pragma unroll
    for (int o = 16; o; o >>= 1) {
        sum += __shfl_xor_sync(0xffffffffu, sum, o);
        sq  += __shfl_xor_sync(0xffffffffu, sq,  o);
    }
    float m   = sum * (1.0f / 128.0f);
    float inv = rsqrtf(sq * (1.0f / 128.0f) - m * m + 1e-5f);
    float4 ao;
    ao.x = (av.x - m) * inv; ao.y = (av.y - m) * inv;
    ao.z = (av.z - m) * inv; ao.w = (av.w - m) * inv;
    ((float4*)(a_n + base))[lane] = ao;

    float4 sv = ((const float4*)(s + base))[lane];
    {
        __half* p = s_rh + base + lane * 4;
        *(__half2*)(p)     = __floats2half2_rn(sv.x, sv.y);
        *(__half2*)(p + 2) = __floats2half2_rn(sv.z, sv.w);
    }

    float sums = sv.x + sv.y + sv.z + sv.w;
    float sqs  = sv.x * sv.x + sv.y * sv.y + sv.z * sv.z + sv.w * sv.w;
#pragma unroll
    for (int o = 16; o; o >>= 1) {
        sums += __shfl_xor_sync(0xffffffffu, sums, o);
        sqs  += __shfl_xor_sync(0xffffffffu, sqs,  o);
    }
    float ms   = sums * (1.0f / 128.0f);
    float invs = rsqrtf(sqs * (1.0f / 128.0f) - ms * ms + 1e-5f);
    float4 sn;
    sn.x = (sv.x - ms) * invs; sn.y = (sv.y - ms) * invs;
    sn.z = (sv.z - ms) * invs; sn.w = (sv.w - ms) * invs;

    float4 g1 = ((const float4*)apbg)[lane];
    float4 g2 = ((const float4*)ctg)[lane];
    {
        __half* p = s_apbh + base + lane * 4;
        *(__half2*)(p)     = __floats2half2_rn(sn.x * g1.x, sn.y * g1.y);
        *(__half2*)(p + 2) = __floats2half2_rn(sn.z * g1.z, sn.w * g1.w);
    }
    {
        __half* p = s_cth + base + lane * 4;
        *(__half2*)(p)     = __floats2half2_rn(sn.x * g2.x, sn.y * g2.y);
        *(__half2*)(p + 2) = __floats2half2_rn(sn.z * g2.z, sn.w * g2.w);
    }
}

// ---------------------------------------------------------------------------
// Multi-segment fp16 GEMM (as round 5, but half-capable epilogue + half G3 loader)
// ---------------------------------------------------------------------------
struct Seg {
    const __half* A;
    const __half* Wt;
    const float*  bias;
    void*         C;
    const __half* e1h;
    const float*  e2;
    int           ldC;
    int           ep;     // 0 none, 1 sigmoid, 2 e1h*acc, 3 e1h*acc+e2
    int           outh;   // 1 = write half
};
struct GemmArgs { Seg seg[8]; };

constexpr int HST = 128 * 72;                 // halves per stage
constexpr int GEMM_SMEM = 4 * HST * 2;        // 73728 bytes

__global__ void __launch_bounds__(256, 2) gemm_h(
    int K, int mode, const __half* __restrict__ U1h, const __half* __restrict__ U2h,
    GemmArgs args)
{
    extern __shared__ __half smh[];
    int tid  = threadIdx.x;
    int warp = tid >> 5, lane = tid & 31;
    int wm = (warp >> 2) * 64;
    int wn = (warp & 3) * 32;
    int gid = lane >> 2, qid = lane & 3;
    int row0 = blockIdx.x * 128;
    int y = blockIdx.y;
    const __half* Aseg = args.seg[y].A;
    const __half* Wt   = args.seg[y].Wt;
    int KT = K >> 6;

    uint32_t smBase = smem_u32(smh);

    auto loadA = [&](int kt, int st) {
        if (mode == 0) {
#pragma unroll
            for (int i = 0; i < 4; i++) {
                int e  = tid + i * 256;
                int r  = e >> 3;
                int c8 = (e & 7) * 8;
                uint32_t dst = smBase + (uint32_t)(st * HST + r * 72 + c8) * 2u;
                cp_async16(dst, Aseg + (size_t)(row0 + r) * K + kt * 64 + c8);
            }
        } else {
            __half* As = smh + st * HST;
#pragma unroll
            for (int i = 0; i < 4; i++) {
                int e  = tid + i * 256;
                int r  = e >> 3;
                int c8 = (e & 7) * 8;
                size_t off = (size_t)(row0 + r) * K + kt * 64 + c8;
                uint4 xu = *(const uint4*)(U1h + off);
                uint4 wu = *(const uint4*)(U2h + off);
                const __half2* xh = (const __half2*)&xu;
                const __half2* wh2 = (const __half2*)&wu;
                __half2 outp[4];
#pragma unroll
                for (int j = 0; j < 4; j++) {
                    float2 xf = __half22float2(xh[j]);
                    float2 wf = __half22float2(wh2[j]);
                    outp[j] = __floats2half2_rn(xf.x * sigmoidf_(xf.x) * wf.x,
                                                xf.y * sigmoidf_(xf.y) * wf.y);
                }
                *(uint4*)(As + r * 72 + c8) = *(uint4*)outp;
            }
        }
    };
    auto loadB = [&](int kt, int st) {
#pragma unroll
        for (int i = 0; i < 4; i++) {
            int e  = tid + i * 256;
            int n  = e >> 3;
            int c8 = (e & 7) * 8;
            uint32_t dst = smBase + (uint32_t)(2 * HST + st * HST + n * 72 + c8) * 2u;
            cp_async16(dst, Wt + (size_t)n * K + kt * 64 + c8);
        }
    };

    float c[4][4][4];
#pragma unroll
    for (int mi = 0; mi < 4; mi++)
#pragma unroll
        for (int ni = 0; ni < 4; ni++)
#pragma unroll
            for (int r = 0; r < 4; r++) c[mi][ni][r] = 0.0f;

    loadA(0, 0); loadB(0, 0); cp_commit();
    if (KT > 1) { loadA(1, 1); loadB(1, 1); cp_commit(); }

    for (int kt = 0; kt < KT; kt++) {
        cp_wait1();
        __syncthreads();
        int st = kt & 1;
        const __half* As = smh + st * HST;
        const __half* Bs = smh + 2 * HST + st * HST;
#pragma unroll
        for (int ks = 0; ks < 4; ks++) {
            int kb = ks * 16;
            uint32_t af[4][4], bf[4][2];
#pragma unroll
            for (int mi = 0; mi < 4; mi++) {
                int ra = (wm + mi * 16 + gid) * 72 + kb + 2 * qid;
                af[mi][0] = *(const uint32_t*)(As + ra);
                af[mi][1] = *(const uint32_t*)(As + ra + 8 * 72);
                af[mi][2] = *(const uint32_t*)(As + ra + 8);
                af[mi][3] = *(const uint32_t*)(As + ra + 8 * 72 + 8);
            }
#pragma unroll
            for (int ni = 0; ni < 4; ni++) {
                int rb = (wn + ni * 8 + gid) * 72 + kb + 2 * qid;
                bf[ni][0] = *(const uint32_t*)(Bs + rb);
                bf[ni][1] = *(const uint32_t*)(Bs + rb + 8);
            }
#pragma unroll
            for (int mi = 0; mi < 4; mi++)
#pragma unroll
                for (int ni = 0; ni < 4; ni++)
                    MMA_F16(c[mi][ni], af[mi], bf[ni]);
        }
        __syncthreads();
        if (kt + 2 < KT) { loadA(kt + 2, st); loadB(kt + 2, st); }
        cp_commit();
    }

    const float* bias = args.seg[y].bias;
    void* C = args.seg[y].C;
    const __half* e1h = args.seg[y].e1h;
    const float* e2 = args.seg[y].e2;
    int ldC = args.seg[y].ldC;
    int ep  = args.seg[y].ep;
    int outh = args.seg[y].outh;

#pragma unroll
    for (int mi = 0; mi < 4; mi++) {
#pragma unroll
        for (int ni = 0; ni < 4; ni++) {
            int rA = row0 + wm + mi * 16 + gid;
            int cc = wn + ni * 8 + qid * 2;
            float b0 = bias ? bias[cc]     : 0.0f;
            float b1 = bias ? bias[cc + 1] : 0.0f;
#pragma unroll
            for (int h = 0; h < 2; h++) {
                size_t idx = (size_t)(rA + h * 8) * ldC + cc;
                float v0 = c[mi][ni][h * 2 + 0] + b0;
                float v1 = c[mi][ni][h * 2 + 1] + b1;
                if (ep == 1)      { v0 = sigmoidf_(v0); v1 = sigmoidf_(v1); }
                else if (ep == 2) {
                    __half2 e = *(const __half2*)(e1h + idx);
                    v0 *= __low2float(e); v1 *= __high2float(e);
                } else if (ep == 3) {
                    __half2 e = *(const __half2*)(e1h + idx);
                    v0 = __low2float(e)  * v0 + e2[idx];
                    v1 = __high2float(e) * v1 + e2[idx + 1];
                }
                if (outh) *(__half2*)((__half*)C + idx) = __floats2half2_rn(v0, v1);
                else      *(float2*)((float*)C + idx)   = make_float2(v0, v1);
            }
        }
    }
}

// ---------------------------------------------------------------------------
// Combine: a1h = h(gapb*a_n + kapb); a3h = h(gct*a_n + kct)  (inputs half)
// ---------------------------------------------------------------------------
__global__ void combine1_kernel(
    const __half* __restrict__ gapbh, const __half* __restrict__ kapbh,
    const __half* __restrict__ gcth,  const __half* __restrict__ kcth,
    const float* __restrict__ a_n,
    __half* __restrict__ a1h, __half* __restrict__ a3h)
{
    size_t i = (size_t)blockIdx.x * blockDim.x + threadIdx.x;  // float4 index
    float4 van = ((const float4*)a_n)[i];

    {
        __half2 g0 = ((const __half2*)gapbh)[2 * i], g1 = ((const __half2*)gapbh)[2 * i + 1];
        __half2 k0 = ((const __half2*)kapbh)[2 * i], k1 = ((const __half2*)kapbh)[2 * i + 1];
        float2 gf0 = __half22float2(g0), gf1 = __half22float2(g1);
        float2 kf0 = __half22float2(k0), kf1 = __half22float2(k1);
        ((__half2*)a1h)[2 * i]     = __floats2half2_rn(gf0.x * van.x + kf0.x, gf0.y * van.y + kf0.y);
        ((__half2*)a1h)[2 * i + 1] = __floats2half2_rn(gf1.x * van.z + kf1.x, gf1.y * van.w + kf1.y);
    }
    {
        __half2 g0 = ((const __half2*)gcth)[2 * i], g1 = ((const __half2*)gcth)[2 * i + 1];
        __half2 k0 = ((const __half2*)kcth)[2 * i], k1 = ((const __half2*)kcth)[2 * i + 1];
        float2 gf0 = __half22float2(g0), gf1 = __half22float2(g1);
        float2 kf0 = __half22float2(k0), kf1 = __half22float2(k1);
        ((__half2*)a3h)[2 * i]     = __floats2half2_rn(gf0.x * van.x + kf0.x, gf0.y * van.y + kf0.y);
        ((__half2*)a3h)[2 * i + 1] = __floats2half2_rn(gf1.x * van.z + kf1.x, gf1.y * van.w + kf1.y);
    }
}

// ---------------------------------------------------------------------------
// Tensor-core local attention. One CTA per (b, nb).
// smem: biasS fp32 [4][32][132], scp fp32 [32][132],
//       Qs/Ks/Vs/Ps half (stride 136).
// ---------------------------------------------------------------------------
constexpr int ATTN_SMEM_BYTES = (4 * 4224 + 4224) * 4 + (4352 + 17408 + 17408 + 4352) * 2;

__global__ void __launch_bounds__(256) attn_kernel(
    const __half* __restrict__ qh, const __half* __restrict__ kh,
    const __half* __restrict__ vh, const float* __restrict__ z,
    const float* __restrict__ gamma_z, const float* __restrict__ Wz,
    const __half* __restrict__ gh, __half* __restrict__ obh)
{
    extern __shared__ float sm[];
    float* biasS = sm;                       // 4*4224 fp32
    float* scp   = sm + 4 * 4224;            // 4224 fp32
    __half* Qs = (__half*)(sm + 5 * 4224);   // 32*136
    __half* Ks = Qs + 4352;                  // 128*136
    __half* Vs = Ks + 17408;                 // 128*136
    __half* Ps = Vs + 17408;                 // 32*136
    __shared__ float gzs[CZ_];
    __shared__ float wzs[CZ_ * H_];

    int tid = threadIdx.x;
    int warp = tid >> 5, lane = tid & 31;
    int gid = lane >> 2, qid = lane & 3;
    int nb = blockIdx.x, b = blockIdx.y;
    if (tid < CZ_)      gzs[tid] = gamma_z[tid];
    if (tid < CZ_ * H_) wzs[tid] = Wz[tid];

    int kbase = nb * 32 - 48;

    // ---- load Q (32x128 half) ----
    for (int e = tid; e < 512; e += 256) {
        int qq = e >> 4, c8 = (e & 15) * 8;
        *(float4*)(Qs + qq * 136 + c8) =
            *(const float4*)(qh + ((size_t)b * N_ + nb * 32 + qq) * 128 + c8);
    }
    // ---- load K/V (128 tokens, clamped) ----
    for (int e = tid; e < 2048; e += 256) {
        int j = e >> 4, c8 = (e & 15) * 8;
        int t = kbase + j;
        t = t < 0 ? 0 : (t >= N_ ? N_ - 1 : t);
        size_t off = ((size_t)b * N_ + t) * 128 + c8;
        *(float4*)(Ks + j * 136 + c8) = *(const float4*)(kh + off);
        *(float4*)(Vs + j * 136 + c8) = *(const float4*)(vh + off);
    }
    __syncthreads();

    // ---- pair bias: LN(z) @ Wz ----
    const float* zb = z + ((size_t)(b * NB_ + nb)) * 4096 * CZ_;
#pragma unroll 1
    for (int i = 0; i < 16; i++) {
        int p = tid + i * 256;
        const float4* zp = (const float4*)(zb + (size_t)p * CZ_);
        float4 z0 = zp[0], z1 = zp[1], z2 = zp[2], z3 = zp[3];
        float zv[16] = {z0.x, z0.y, z0.z, z0.w, z1.x, z1.y, z1.z, z1.w,
                        z2.x, z2.y, z2.z, z2.w, z3.x, z3.y, z3.z, z3.w};
        float mm = 0.0f;
#pragma unroll
        for (int c = 0; c < 16; c++) mm += zv[c];
        mm *= (1.0f / 16.0f);
        float ss2 = 0.0f;
#pragma unroll
        for (int c = 0; c < 16; c++) { float d = zv[c] - mm; ss2 += d * d; }
        float inv = rsqrtf(ss2 * (1.0f / 16.0f) + 1e-5f);
        float bh0 = 0, bh1 = 0, bh2 = 0, bh3 = 0;
#pragma unroll
        for (int c = 0; c < 16; c++) {
            float zn = (zv[c] - mm) * inv * gzs[c];
            bh0 += zn * wzs[c * 4 + 0];
            bh1 += zn * wzs[c * 4 + 1];
            bh2 += zn * wzs[c * 4 + 2];
            bh3 += zn * wzs[c * 4 + 3];
        }
        int qq = p >> 7, kk = p & 127;
        int o2 = qq * 132 + kk;
        biasS[0 * 4224 + o2] = bh0;
        biasS[1 * 4224 + o2] = bh1;
        biasS[2 * 4224 + o2] = bh2;
        biasS[3 * 4224 + o2] = bh3;
    }
    __syncthreads();

    uint32_t vsBase = smem_u32(Vs);
    const float SCALE = 0.17677669529663687f;

    for (int h = 0; h < H_; h++) {
        // ---- scores: S = Q_h @ K_h^T (32x128), warp = (m half, 32-key band) ----
        {
            int m0 = (warp >> 2) * 16;
            int n0 = (warp & 3) * 32;
            float c[4][4];
#pragma unroll
            for (int nt = 0; nt < 4; nt++)
#pragma unroll
                for (int r = 0; r < 4; r++) c[nt][r] = 0.0f;
#pragma unroll
            for (int ks = 0; ks < 2; ks++) {
                int kb = ks * 16;
                int ra = (m0 + gid) * 136 + h * 32 + kb + 2 * qid;
                uint32_t af[4];
                af[0] = *(const uint32_t*)(Qs + ra);
                af[1] = *(const uint32_t*)(Qs + ra + 8 * 136);
                af[2] = *(const uint32_t*)(Qs + ra + 8);
                af[3] = *(const uint32_t*)(Qs + ra + 8 * 136 + 8);
#pragma unroll
                for (int nt = 0; nt < 4; nt++) {
                    int rb = (n0 + nt * 8 + gid) * 136 + h * 32 + kb + 2 * qid;
                    uint32_t bf[2];
                    bf[0] = *(const uint32_t*)(Ks + rb);
                    bf[1] = *(const uint32_t*)(Ks + rb + 8);
                    MMA_F16(c[nt], af, bf);
                }
            }
#pragma unroll
            for (int nt = 0; nt < 4; nt++) {
                int col = n0 + nt * 8 + 2 * qid;
                int r0 = m0 + gid, r1 = r0 + 8;
                bool ok0 = (kbase + col >= 0) && (kbase + col < N_);
                bool ok1 = (kbase + col + 1 >= 0) && (kbase + col + 1 < N_);
                const float* bh = biasS + h * 4224;
                scp[r0 * 132 + col]     = ok0 ? c[nt][0] * SCALE + bh[r0 * 132 + col]     : -1e9f;
                scp[r0 * 132 + col + 1] = ok1 ? c[nt][1] * SCALE + bh[r0 * 132 + col + 1] : -1e9f;
                scp[r1 * 132 + col]     = ok0 ? c[nt][2] * SCALE + bh[r1 * 132 + col]     : -1e9f;
                scp[r1 * 132 + col + 1] = ok1 ? c[nt][3] * SCALE + bh[r1 * 132 + col + 1] : -1e9f;
            }
        }
        __syncthreads();

        // ---- softmax (fp32), write P as half ----
#pragma unroll
        for (int rr = 0; rr < 4; rr++) {
            int r = warp * 4 + rr;
            const float* row = scp + r * 132;
            float v0 = row[lane], v1 = row[lane + 32], v2 = row[lane + 64], v3 = row[lane + 96];
            float mx = fmaxf(fmaxf(v0, v1), fmaxf(v2, v3));
#pragma unroll
            for (int o2 = 16; o2; o2 >>= 1) mx = fmaxf(mx, __shfl_xor_sync(0xffffffffu, mx, o2));
            v0 = __expf(v0 - mx); v1 = __expf(v1 - mx);
            v2 = __expf(v2 - mx); v3 = __expf(v3 - mx);
            float sumv = v0 + v1 + v2 + v3;
#pragma unroll
            for (int o2 = 16; o2; o2 >>= 1) sumv += __shfl_xor_sync(0xffffffffu, sumv, o2);
            float invs = 1.0f / sumv;
            __half* pr = Ps + r * 136;
            pr[lane]      = __float2half(v0 * invs);
            pr[lane + 32] = __float2half(v1 * invs);
            pr[lane + 64] = __float2half(v2 * invs);
            pr[lane + 96] = __float2half(v3 * invs);
        }
        __syncthreads();

        // ---- PV: O = P @ V_h (32x32), warp = (m half, 8-dim band) ----
        {
            int m0 = (warp >> 2) * 16;
            int nd0 = (warp & 3) * 8;
            float o[4] = {0.0f, 0.0f, 0.0f, 0.0f};
#pragma unroll
            for (int kb = 0; kb < 8; kb++) {
                int ra = (m0 + gid) * 136 + kb * 16 + 2 * qid;
                uint32_t af[4];
                af[0] = *(const uint32_t*)(Ps + ra);
                af[1] = *(const uint32_t*)(Ps + ra + 8 * 136);
                af[2] = *(const uint32_t*)(Ps + ra + 8);
                af[3] = *(const uint32_t*)(Ps + ra + 8 * 136 + 8);
                // B fragment from row-major V [key][dim] via ldmatrix.x2.trans
                int l = lane & 15;
                uint32_t addr = vsBase + (uint32_t)((kb * 16 + l) * 136 + h * 32 + nd0) * 2u;
                uint32_t bf0, bf1;
                asm volatile("ldmatrix.sync.aligned.m8n8.x2.trans.shared.b16 {%0,%1}, [%2];"
                             : "=r"(bf0), "=r"(bf1) : "r"(addr));
                uint32_t bf[2] = {bf0, bf1};
                MMA_F16(o, af, bf);
            }
            int r0 = m0 + gid;
            size_t t0 = ((size_t)b * N_ + nb * 32 + r0) * 128 + h * 32 + nd0 + 2 * qid;
            size_t t1 = t0 + (size_t)8 * 128;
            float2 g0 = __half22float2(*(const __half2*)(gh + t0));
            float2 g1 = __half22float2(*(const __half2*)(gh + t1));
            *(__half2*)(obh + t0) = __floats2half2_rn(g0.x * o[0], g0.y * o[1]);
            *(__half2*)(obh + t1) = __floats2half2_rn(g1.x * o[2], g1.y * o[3]);
        }
        __syncthreads();
    }
}

// ---------------------------------------------------------------------------
// Host launch
// ---------------------------------------------------------------------------
extern "C" void kernel_launch(void* const* d_in, const int* in_sizes, int n_in,
                              void* d_out, int out_size)
{
    const float* a       = (const float*)d_in[0];
    const float* s       = (const float*)d_in[1];
    const float* z       = (const float*)d_in[2];
    const float* apb_gam = (const float*)d_in[3];
    const float* apb_Wg  = (const float*)d_in[4];
    const float* apb_bg  = (const float*)d_in[5];
    const float* apb_Wsk = (const float*)d_in[6];
    const float* Wq      = (const float*)d_in[7];
    const float* bq      = (const float*)d_in[8];
    const float* Wk      = (const float*)d_in[9];
    const float* Wv      = (const float*)d_in[10];
    const float* Wgate   = (const float*)d_in[11];
    const float* Wo      = (const float*)d_in[12];
    const float* gamma_z = (const float*)d_in[13];
    const float* Wz      = (const float*)d_in[14];
    const float* Ws_last = (const float*)d_in[15];
    const float* bs_last = (const float*)d_in[16];
    const float* ct_gam  = (const float*)d_in[17];
    const float* ct_Wg   = (const float*)d_in[18];
    const float* ct_bg   = (const float*)d_in[19];
    const float* ct_Wsk  = (const float*)d_in[20];
    const float* Wa1     = (const float*)d_in[21];
    const float* Wa2     = (const float*)d_in[22];
    const float* Wb      = (const float*)d_in[23];
    const float* Ws      = (const float*)d_in[24];
    const float* bsv     = (const float*)d_in[25];
    float* out = (float*)d_out;

    float* S = nullptr;
    cudaGetSymbolAddress((void**)&S, g_scratch);
    // fp32 slots 0-1
    float* a_n = S;
    float* ctp = S + SLOT;
    // half region from slot 2
    __half* HB = (__half*)(S + 2 * SLOT);
    auto hslot = [&](int k) { return HB + (size_t)k * SLOT; };  // SLOT halves each
    __half* u1h    = hslot(0);   // M x 256 (2 half-slots)
    __half* u2h    = hslot(2);   // M x 256
    __half* s_apbh = hslot(4);
    __half* s_cth  = hslot(5);
    __half* s_rh   = hslot(6);
    __half* a1h    = hslot(7);
    __half* a3h    = hslot(8);
    __half* obh    = hslot(9);
    __half* gapbh  = hslot(10);
    __half* kapbh  = hslot(11);
    __half* gcth   = hslot(12);
    __half* kcth   = hslot(13);
    __half* glasth = hslot(14);
    __half* sgh    = hslot(15);
    __half* qh     = hslot(16);
    __half* khb    = hslot(17);
    __half* vhb    = hslot(18);
    __half* ghb    = hslot(19);
    __half* wh     = hslot(20);  // weights

    __half* wWg   = wh + 0;
    __half* wWsk  = wh + 16384;
    __half* wcWg  = wh + 32768;
    __half* wcWsk = wh + 49152;
    __half* wWsl  = wh + 65536;
    __half* wWs   = wh + 81920;
    __half* wWq   = wh + 98304;
    __half* wWk   = wh + 114688;
    __half* wWv   = wh + 131072;
    __half* wWgt  = wh + 147456;
    __half* wWo   = wh + 163840;
    __half* wWa1  = wh + 180224;  // [256][128]
    __half* wWa2  = wh + 212992;
    __half* wWb   = wh + 245760;  // [128][256]

    WtPack wp;
    const float* wsrc[14] = {apb_Wg, apb_Wsk, ct_Wg, ct_Wsk, Ws_last, Ws, Wq, Wk, Wv,
                             Wgate, Wo, Wa1, Wa2, Wb};
    __half* wdst[14] = {wWg, wWsk, wcWg, wcWsk, wWsl, wWs, wWq, wWk, wWv,
                        wWgt, wWo, wWa1, wWa2, wWb};
    int wK[14] = {128,128,128,128,128,128,128,128,128,128,128,128,128,256};
    int wN[14] = {128,128,128,128,128,128,128,128,128,128,128,256,256,128};
    for (int i = 0; i < 14; i++) { wp.src[i] = wsrc[i]; wp.dst[i] = wdst[i];
                                   wp.K[i] = wK[i]; wp.N[i] = wN[i]; }
    cvtw_kernel<<<dim3(16, 14), 256>>>(wp);

    ln_kernel<<<M_ / 8, 256>>>(a, s, apb_gam, ct_gam, a_n, s_apbh, s_cth, s_rh);

    cudaFuncSetAttribute(gemm_h, cudaFuncAttributeMaxDynamicSharedMemorySize, GEMM_SMEM);
    cudaFuncSetAttribute(attn_kernel, cudaFuncAttributeMaxDynamicSharedMemorySize,
                         ATTN_SMEM_BYTES);

    auto mkseg = [&](const __half* A, const __half* Wt, const float* bias, void* C,
                     int ep, const __half* e1h, const float* e2, int ldC, int outh) {
        Seg sgm; sgm.A = A; sgm.Wt = Wt; sgm.bias = bias; sgm.C = C;
        sgm.e1h = e1h; sgm.e2 = e2; sgm.ldC = ldC; sgm.ep = ep; sgm.outh = outh;
        return sgm;
    };

    // G1: 6 segments from s-derived activations (all half outputs)
    {
        GemmArgs g{};
        g.seg[0] = mkseg(s_apbh, wWg,   apb_bg,  gapbh,  1, nullptr, nullptr, 128, 1);
        g.seg[1] = mkseg(s_apbh, wWsk,  nullptr, kapbh,  0, nullptr, nullptr, 128, 1);
        g.seg[2] = mkseg(s_cth,  wcWg,  ct_bg,   gcth,   1, nullptr, nullptr, 128, 1);
        g.seg[3] = mkseg(s_cth,  wcWsk, nullptr, kcth,   0, nullptr, nullptr, 128, 1);
        g.seg[4] = mkseg(s_rh,   wWsl,  bs_last, glasth, 1, nullptr, nullptr, 128, 1);
        g.seg[5] = mkseg(s_rh,   wWs,   bsv,     sgh,    1, nullptr, nullptr, 128, 1);
        gemm_h<<<dim3(M_ / 128, 6), 256, GEMM_SMEM>>>(128, 0, nullptr, nullptr, g);
    }

    combine1_kernel<<<(int)(SLOT / 4 / 256), 256>>>(gapbh, kapbh, gcth, kcth, a_n, a1h, a3h);

    // G2: qkv/gate from a1h; u1/u2 from a3h (all half outputs)
    {
        GemmArgs g{};
        g.seg[0] = mkseg(a1h, wWq,          bq,      qh,        0, nullptr, nullptr, 128, 1);
        g.seg[1] = mkseg(a1h, wWk,          nullptr, khb,       0, nullptr, nullptr, 128, 1);
        g.seg[2] = mkseg(a1h, wWv,          nullptr, vhb,       0, nullptr, nullptr, 128, 1);
        g.seg[3] = mkseg(a1h, wWgt,         nullptr, ghb,       1, nullptr, nullptr, 128, 1);
        g.seg[4] = mkseg(a3h, wWa1,         nullptr, u1h,       0, nullptr, nullptr, 256, 1);
        g.seg[5] = mkseg(a3h, wWa1 + 16384, nullptr, u1h + 128, 0, nullptr, nullptr, 256, 1);
        g.seg[6] = mkseg(a3h, wWa2,         nullptr, u2h,       0, nullptr, nullptr, 256, 1);
        g.seg[7] = mkseg(a3h, wWa2 + 16384, nullptr, u2h + 128, 0, nullptr, nullptr, 256, 1);
        gemm_h<<<dim3(M_ / 128, 8), 256, GEMM_SMEM>>>(128, 0, nullptr, nullptr, g);
    }

    // G3: ct_out = sgh * (silu(u1)*u2 @ Wb), K=256, silu fused into loader, fp32 out
    {
        GemmArgs g{};
        g.seg[0] = mkseg(nullptr, wWb, nullptr, ctp, 2, sgh, nullptr, 128, 0);
        gemm_h<<<dim3(M_ / 128, 1), 256, GEMM_SMEM>>>(256, 1, u1h, u2h, g);
    }

    // attention (tensor-core, gate fused, half out)
    attn_kernel<<<dim3(NB_, B_), 256, ATTN_SMEM_BYTES>>>(
        qh, khb, vhb, z, gamma_z, Wz, ghb, obh);

    // G4: out = glasth * (obh @ Wo) + ctp  (fp32 out)
    {
        GemmArgs g{};
        g.seg[0] = mkseg(obh, wWo, nullptr, out, 3, glasth, ctp, 128, 0);
        gemm_h<<<dim3(M_ / 128, 1), 256, GEMM_SMEM>>>(128, 0, nullptr, nullptr, g);
    }
}

// round 10
// speedup vs baseline: 3.2930x; 1.0375x over previous
#include <cuda_runtime.h>
#include <cuda_fp16.h>
#include <cstdint>

// ---------------------------------------------------------------------------
// AtomAttentionEncoder fused pipeline (round 9: ldmatrix fragment loads)
// B=2, N=16384, CA=CS=128, CZ=16, H=4, NQ=32, NK=128, DH=32, NB=512
// ---------------------------------------------------------------------------

constexpr int B_  = 2;
constexpr int N_  = 16384;
constexpr int CA_ = 128;
constexpr int CZ_ = 16;
constexpr int H_  = 4;
constexpr int NB_ = 512;

constexpr int    M_   = B_ * N_;               // 32768 tokens
constexpr size_t SLOT = (size_t)M_ * CA_;      // 4,194,304 floats

__device__ float g_scratch[13 * SLOT];

__device__ __forceinline__ float sigmoidf_(float x) { return 1.0f / (1.0f + __expf(-x)); }

#define MMA_F16(cc, aa, bb)                                                    \
    asm volatile("mma.sync.aligned.m16n8k16.row.col.f32.f16.f16.f32 "          \
                 "{%0,%1,%2,%3}, {%4,%5,%6,%7}, {%8,%9}, {%0,%1,%2,%3};"       \
                 : "+f"(cc[0]), "+f"(cc[1]), "+f"(cc[2]), "+f"(cc[3])          \
                 : "r"(aa[0]), "r"(aa[1]), "r"(aa[2]), "r"(aa[3]),             \
                   "r"(bb[0]), "r"(bb[1]))

__device__ __forceinline__ void cp_async16(uint32_t smem_addr, const void* gptr) {
    asm volatile("cp.async.cg.shared.global [%0], [%1], 16;\n"
                 :: "r"(smem_addr), "l"(gptr));
}
__device__ __forceinline__ void cp_commit() { asm volatile("cp.async.commit_group;\n"); }
__device__ __forceinline__ void cp_wait1()  { asm volatile("cp.async.wait_group 1;\n"); }

__device__ __forceinline__ uint32_t smem_u32(const void* p) {
    uint32_t a;
    asm("{ .reg .u64 t; cvta.to.shared.u64 t, %1; cvt.u32.u64 %0, t; }" : "=r"(a) : "l"(p));
    return a;
}
__device__ __forceinline__ void ldsm_x4(uint32_t (&r)[4], uint32_t addr) {
    asm volatile("ldmatrix.sync.aligned.m8n8.x4.shared.b16 {%0,%1,%2,%3}, [%4];"
                 : "=r"(r[0]), "=r"(r[1]), "=r"(r[2]), "=r"(r[3]) : "r"(addr));
}
__device__ __forceinline__ void ldsm_x2(uint32_t (&r)[2], uint32_t addr) {
    asm volatile("ldmatrix.sync.aligned.m8n8.x2.shared.b16 {%0,%1}, [%2];"
                 : "=r"(r[0]), "=r"(r[1]) : "r"(addr));
}

// ---------------------------------------------------------------------------
// Weight conversion: Wt[n*K + k] = half(W[k*N + n])
// ---------------------------------------------------------------------------
struct WtPack {
    const float* src[14];
    __half*      dst[14];
    int          K[14];
    int          N[14];
};
__global__ void cvtw_kernel(WtPack p)
{
    int y = blockIdx.y;
    int K = p.K[y], N = p.N[y];
    const float* s = p.src[y];
    __half* d = p.dst[y];
    int total = K * N;
    for (int i = blockIdx.x * 256 + threadIdx.x; i < total; i += gridDim.x * 256) {
        int k = i / N, n = i % N;
        d[n * K + k] = __float2half(s[i]);
    }
}

// ---------------------------------------------------------------------------
// LayerNorm
// ---------------------------------------------------------------------------
__global__ void ln_kernel(const float* __restrict__ a, const float* __restrict__ s,
                          const float* __restrict__ apbg, const float* __restrict__ ctg,
                          float* __restrict__ a_n, __half* __restrict__ s_apbh,
                          __half* __restrict__ s_cth, __half* __restrict__ s_rh)
{
    int warp = (blockIdx.x * blockDim.x + threadIdx.x) >> 5;
    int lane = threadIdx.x & 31;
    if (warp >= M_) return;
    size_t base = (size_t)warp * CA_;

    float4 av = ((const float4*)(a + base))[lane];
    float sum = av.x + av.y + av.z + av.w;
    float sq  = av.x * av.x + av.y * av.y + av.z * av.z + av.w * av.w;
#pragma unroll
    for (int o = 16; o; o >>= 1) {
        sum += __shfl_xor_sync(0xffffffffu, sum, o);
        sq  += __shfl_xor_sync(0xffffffffu, sq,  o);
    }
    float m   = sum * (1.0f / 128.0f);
    float inv = rsqrtf(sq * (1.0f / 128.0f) - m * m + 1e-5f);
    float4 ao;
    ao.x = (av.x - m) * inv; ao.y = (av.y - m) * inv;
    ao.z = (av.z - m) * inv; ao.w = (av.w - m) * inv;
    ((float4*)(a_n + base))[lane] = ao;

    float4 sv = ((const float4*)(s + base))[lane];
    {
        __half* p = s_rh + base + lane * 4;
        *(__half2*)(p)     = __floats2half2_rn(sv.x, sv.y);
        *(__half2*)(p + 2) = __floats2half2_rn(sv.z, sv.w);
    }

    float sums = sv.x + sv.y + sv.z + sv.w;
    float sqs  = sv.x * sv.x + sv.y * sv.y + sv.z * sv.z + sv.w * sv.w;
#pragma unroll
    for (int o = 16; o; o >>= 1) {
        sums += __shfl_xor_sync(0xffffffffu, sums, o);
        sqs  += __shfl_xor_sync(0xffffffffu, sqs,  o);
    }
    float ms   = sums * (1.0f / 128.0f);
    float invs = rsqrtf(sqs * (1.0f / 128.0f) - ms * ms + 1e-5f);
    float4 sn;
    sn.x = (sv.x - ms) * invs; sn.y = (sv.y - ms) * invs;
    sn.z = (sv.z - ms) * invs; sn.w = (sv.w - ms) * invs;

    float4 g1 = ((const float4*)apbg)[lane];
    float4 g2 = ((const float4*)ctg)[lane];
    {
        __half* p = s_apbh + base + lane * 4;
        *(__half2*)(p)     = __floats2half2_rn(sn.x * g1.x, sn.y * g1.y);
        *(__half2*)(p + 2) = __floats2half2_rn(sn.z * g1.z, sn.w * g1.w);
    }
    {
        __half* p = s_cth + base + lane * 4;
        *(__half2*)(p)     = __floats2half2_rn(sn.x * g2.x, sn.y * g2.y);
        *(__half2*)(p + 2) = __floats2half2_rn(sn.z * g2.z, sn.w * g2.w);
    }
}

// ---------------------------------------------------------------------------
// Multi-segment fp16 GEMM with ldmatrix fragment loads.
// ---------------------------------------------------------------------------
struct Seg {
    const __half* A;
    const __half* Wt;
    const float*  bias;
    void*         C;
    const __half* e1h;
    const float*  e2;
    int           ldC;
    int           ep;     // 0 none, 1 sigmoid, 2 e1h*acc, 3 e1h*acc+e2
    int           outh;   // 1 = write half
};
struct GemmArgs { Seg seg[8]; };

constexpr int HST = 128 * 72;                 // halves per stage
constexpr int GEMM_SMEM = 4 * HST * 2;        // 73728 bytes

__global__ void __launch_bounds__(256, 2) gemm_h(
    int K, int mode, const __half* __restrict__ U1h, const __half* __restrict__ U2h,
    GemmArgs args)
{
    extern __shared__ __half smh[];
    int tid  = threadIdx.x;
    int warp = tid >> 5, lane = tid & 31;
    int wm = (warp >> 2) * 64;
    int wn = (warp & 3) * 32;
    int gid = lane >> 2, qid = lane & 3;
    int row0 = blockIdx.x * 128;
    int y = blockIdx.y;
    const __half* Aseg = args.seg[y].A;
    const __half* Wt   = args.seg[y].Wt;
    int KT = K >> 6;

    uint32_t smBase = smem_u32(smh);
    int lmA = lane & 15, lhA = (lane >> 4) << 3;        // x4 addressing
    int lmB = lane & 7,  lhB = ((lane >> 3) & 1) << 3;  // x2 addressing

    auto loadA = [&](int kt, int st) {
        if (mode == 0) {
#pragma unroll
            for (int i = 0; i < 4; i++) {
                int e  = tid + i * 256;
                int r  = e >> 3;
                int c8 = (e & 7) * 8;
                uint32_t dst = smBase + (uint32_t)(st * HST + r * 72 + c8) * 2u;
                cp_async16(dst, Aseg + (size_t)(row0 + r) * K + kt * 64 + c8);
            }
        } else {
            __half* As = smh + st * HST;
#pragma unroll
            for (int i = 0; i < 4; i++) {
                int e  = tid + i * 256;
                int r  = e >> 3;
                int c8 = (e & 7) * 8;
                size_t off = (size_t)(row0 + r) * K + kt * 64 + c8;
                uint4 xu = *(const uint4*)(U1h + off);
                uint4 wu = *(const uint4*)(U2h + off);
                const __half2* xh = (const __half2*)&xu;
                const __half2* wh2 = (const __half2*)&wu;
                __half2 outp[4];
#pragma unroll
                for (int j = 0; j < 4; j++) {
                    float2 xf = __half22float2(xh[j]);
                    float2 wf = __half22float2(wh2[j]);
                    outp[j] = __floats2half2_rn(xf.x * sigmoidf_(xf.x) * wf.x,
                                                xf.y * sigmoidf_(xf.y) * wf.y);
                }
                *(uint4*)(As + r * 72 + c8) = *(uint4*)outp;
            }
        }
    };
    auto loadB = [&](int kt, int st) {
#pragma unroll
        for (int i = 0; i < 4; i++) {
            int e  = tid + i * 256;
            int n  = e >> 3;
            int c8 = (e & 7) * 8;
            uint32_t dst = smBase + (uint32_t)(2 * HST + st * HST + n * 72 + c8) * 2u;
            cp_async16(dst, Wt + (size_t)n * K + kt * 64 + c8);
        }
    };

    float c[4][4][4];
#pragma unroll
    for (int mi = 0; mi < 4; mi++)
#pragma unroll
        for (int ni = 0; ni < 4; ni++)
#pragma unroll
            for (int r = 0; r < 4; r++) c[mi][ni][r] = 0.0f;

    loadA(0, 0); loadB(0, 0); cp_commit();
    if (KT > 1) { loadA(1, 1); loadB(1, 1); cp_commit(); }

    for (int kt = 0; kt < KT; kt++) {
        cp_wait1();
        __syncthreads();
        int st = kt & 1;
        uint32_t asB = smBase + (uint32_t)(st * HST) * 2u;
        uint32_t bsB = smBase + (uint32_t)(2 * HST + st * HST) * 2u;
#pragma unroll
        for (int ks = 0; ks < 4; ks++) {
            int kb = ks * 16;
            uint32_t af[4][4], bf[4][2];
#pragma unroll
            for (int mi = 0; mi < 4; mi++)
                ldsm_x4(af[mi], asB + (uint32_t)((wm + mi * 16 + lmA) * 72 + kb + lhA) * 2u);
#pragma unroll
            for (int ni = 0; ni < 4; ni++)
                ldsm_x2(bf[ni], bsB + (uint32_t)((wn + ni * 8 + lmB) * 72 + kb + lhB) * 2u);
#pragma unroll
            for (int mi = 0; mi < 4; mi++)
#pragma unroll
                for (int ni = 0; ni < 4; ni++)
                    MMA_F16(c[mi][ni], af[mi], bf[ni]);
        }
        __syncthreads();
        if (kt + 2 < KT) { loadA(kt + 2, st); loadB(kt + 2, st); }
        cp_commit();
    }

    const float* bias = args.seg[y].bias;
    void* C = args.seg[y].C;
    const __half* e1h = args.seg[y].e1h;
    const float* e2 = args.seg[y].e2;
    int ldC = args.seg[y].ldC;
    int ep  = args.seg[y].ep;
    int outh = args.seg[y].outh;

#pragma unroll
    for (int mi = 0; mi < 4; mi++) {
#pragma unroll
        for (int ni = 0; ni < 4; ni++) {
            int rA = row0 + wm + mi * 16 + gid;
            int cc = wn + ni * 8 + qid * 2;
            float b0 = bias ? bias[cc]     : 0.0f;
            float b1 = bias ? bias[cc + 1] : 0.0f;
#pragma unroll
            for (int h = 0; h < 2; h++) {
                size_t idx = (size_t)(rA + h * 8) * ldC + cc;
                float v0 = c[mi][ni][h * 2 + 0] + b0;
                float v1 = c[mi][ni][h * 2 + 1] + b1;
                if (ep == 1)      { v0 = sigmoidf_(v0); v1 = sigmoidf_(v1); }
                else if (ep == 2) {
                    __half2 e = *(const __half2*)(e1h + idx);
                    v0 *= __low2float(e); v1 *= __high2float(e);
                } else if (ep == 3) {
                    __half2 e = *(const __half2*)(e1h + idx);
                    v0 = __low2float(e)  * v0 + e2[idx];
                    v1 = __high2float(e) * v1 + e2[idx + 1];
                }
                if (outh) *(__half2*)((__half*)C + idx) = __floats2half2_rn(v0, v1);
                else      *(float2*)((float*)C + idx)   = make_float2(v0, v1);
            }
        }
    }
}

// ---------------------------------------------------------------------------
// Combine: a1h = h(gapb*a_n + kapb); a3h = h(gct*a_n + kct)
// ---------------------------------------------------------------------------
__global__ void combine1_kernel(
    const __half* __restrict__ gapbh, const __half* __restrict__ kapbh,
    const __half* __restrict__ gcth,  const __half* __restrict__ kcth,
    const float* __restrict__ a_n,
    __half* __restrict__ a1h, __half* __restrict__ a3h)
{
    size_t i = (size_t)blockIdx.x * blockDim.x + threadIdx.x;
    float4 van = ((const float4*)a_n)[i];

    {
        __half2 g0 = ((const __half2*)gapbh)[2 * i], g1 = ((const __half2*)gapbh)[2 * i + 1];
        __half2 k0 = ((const __half2*)kapbh)[2 * i], k1 = ((const __half2*)kapbh)[2 * i + 1];
        float2 gf0 = __half22float2(g0), gf1 = __half22float2(g1);
        float2 kf0 = __half22float2(k0), kf1 = __half22float2(k1);
        ((__half2*)a1h)[2 * i]     = __floats2half2_rn(gf0.x * van.x + kf0.x, gf0.y * van.y + kf0.y);
        ((__half2*)a1h)[2 * i + 1] = __floats2half2_rn(gf1.x * van.z + kf1.x, gf1.y * van.w + kf1.y);
    }
    {
        __half2 g0 = ((const __half2*)gcth)[2 * i], g1 = ((const __half2*)gcth)[2 * i + 1];
        __half2 k0 = ((const __half2*)kcth)[2 * i], k1 = ((const __half2*)kcth)[2 * i + 1];
        float2 gf0 = __half22float2(g0), gf1 = __half22float2(g1);
        float2 kf0 = __half22float2(k0), kf1 = __half22float2(k1);
        ((__half2*)a3h)[2 * i]     = __floats2half2_rn(gf0.x * van.x + kf0.x, gf0.y * van.y + kf0.y);
        ((__half2*)a3h)[2 * i + 1] = __floats2half2_rn(gf1.x * van.z + kf1.x, gf1.y * van.w + kf1.y);
    }
}

// ---------------------------------------------------------------------------
// Tensor-core local attention (ldmatrix fragments everywhere).
// ---------------------------------------------------------------------------
constexpr int ATTN_SMEM_BYTES = (4 * 4224 + 4224) * 4 + (4352 + 17408 + 17408 + 4352) * 2;

__global__ void __launch_bounds__(256) attn_kernel(
    const __half* __restrict__ qh, const __half* __restrict__ kh,
    const __half* __restrict__ vh, const float* __restrict__ z,
    const float* __restrict__ gamma_z, const float* __restrict__ Wz,
    const __half* __restrict__ gh, __half* __restrict__ obh)
{
    extern __shared__ float sm[];
    float* biasS = sm;                       // 4*4224 fp32
    float* scp   = sm + 4 * 4224;            // 4224 fp32
    __half* Qs = (__half*)(sm + 5 * 4224);   // 32*136
    __half* Ks = Qs + 4352;                  // 128*136
    __half* Vs = Ks + 17408;                 // 128*136
    __half* Ps = Vs + 17408;                 // 32*136
    __shared__ float gzs[CZ_];
    __shared__ float wzs[CZ_ * H_];

    int tid = threadIdx.x;
    int warp = tid >> 5, lane = tid & 31;
    int gid = lane >> 2, qid = lane & 3;
    int nb = blockIdx.x, b = blockIdx.y;
    if (tid < CZ_)      gzs[tid] = gamma_z[tid];
    if (tid < CZ_ * H_) wzs[tid] = Wz[tid];

    int kbase = nb * 32 - 48;
    int lmA = lane & 15, lhA = (lane >> 4) << 3;
    int lmB = lane & 7,  lhB = ((lane >> 3) & 1) << 3;

    // ---- load Q/K/V ----
    for (int e = tid; e < 512; e += 256) {
        int qq = e >> 4, c8 = (e & 15) * 8;
        *(float4*)(Qs + qq * 136 + c8) =
            *(const float4*)(qh + ((size_t)b * N_ + nb * 32 + qq) * 128 + c8);
    }
    for (int e = tid; e < 2048; e += 256) {
        int j = e >> 4, c8 = (e & 15) * 8;
        int t = kbase + j;
        t = t < 0 ? 0 : (t >= N_ ? N_ - 1 : t);
        size_t off = ((size_t)b * N_ + t) * 128 + c8;
        *(float4*)(Ks + j * 136 + c8) = *(const float4*)(kh + off);
        *(float4*)(Vs + j * 136 + c8) = *(const float4*)(vh + off);
    }
    __syncthreads();

    // ---- pair bias: LN(z) @ Wz ----
    const float* zb = z + ((size_t)(b * NB_ + nb)) * 4096 * CZ_;
#pragma unroll 2
    for (int i = 0; i < 16; i++) {
        int p = tid + i * 256;
        const float4* zp = (const float4*)(zb + (size_t)p * CZ_);
        float4 z0 = zp[0], z1 = zp[1], z2 = zp[2], z3 = zp[3];
        float zv[16] = {z0.x, z0.y, z0.z, z0.w, z1.x, z1.y, z1.z, z1.w,
                        z2.x, z2.y, z2.z, z2.w, z3.x, z3.y, z3.z, z3.w};
        float mm = 0.0f;
#pragma unroll
        for (int c = 0; c < 16; c++) mm += zv[c];
        mm *= (1.0f / 16.0f);
        float ss2 = 0.0f;
#pragma unroll
        for (int c = 0; c < 16; c++) { float d = zv[c] - mm; ss2 += d * d; }
        float inv = rsqrtf(ss2 * (1.0f / 16.0f) + 1e-5f);
        float bh0 = 0, bh1 = 0, bh2 = 0, bh3 = 0;
#pragma unroll
        for (int c = 0; c < 16; c++) {
            float zn = (zv[c] - mm) * inv * gzs[c];
            bh0 += zn * wzs[c * 4 + 0];
            bh1 += zn * wzs[c * 4 + 1];
            bh2 += zn * wzs[c * 4 + 2];
            bh3 += zn * wzs[c * 4 + 3];
        }
        int qq = p >> 7, kk = p & 127;
        int o2 = qq * 132 + kk;
        biasS[0 * 4224 + o2] = bh0;
        biasS[1 * 4224 + o2] = bh1;
        biasS[2 * 4224 + o2] = bh2;
        biasS[3 * 4224 + o2] = bh3;
    }
    __syncthreads();

    uint32_t qsBase = smem_u32(Qs);
    uint32_t ksBase = smem_u32(Ks);
    uint32_t vsBase = smem_u32(Vs);
    uint32_t psBase = smem_u32(Ps);
    const float SCALE = 0.17677669529663687f;

    for (int h = 0; h < H_; h++) {
        // ---- scores: S = Q_h @ K_h^T (32x128) ----
        {
            int m0 = (warp >> 2) * 16;
            int n0 = (warp & 3) * 32;
            float c[4][4];
#pragma unroll
            for (int nt = 0; nt < 4; nt++)
#pragma unroll
                for (int r = 0; r < 4; r++) c[nt][r] = 0.0f;
#pragma unroll
            for (int ks = 0; ks < 2; ks++) {
                int kb = ks * 16;
                uint32_t af[4];
                ldsm_x4(af, qsBase + (uint32_t)((m0 + lmA) * 136 + h * 32 + kb + lhA) * 2u);
#pragma unroll
                for (int nt = 0; nt < 4; nt++) {
                    uint32_t bf[2];
                    ldsm_x2(bf, ksBase + (uint32_t)((n0 + nt * 8 + lmB) * 136 + h * 32 + kb + lhB) * 2u);
                    MMA_F16(c[nt], af, bf);
                }
            }
#pragma unroll
            for (int nt = 0; nt < 4; nt++) {
                int col = n0 + nt * 8 + 2 * qid;
                int r0 = m0 + gid, r1 = r0 + 8;
                bool ok0 = (kbase + col >= 0) && (kbase + col < N_);
                bool ok1 = (kbase + col + 1 >= 0) && (kbase + col + 1 < N_);
                const float* bh = biasS + h * 4224;
                scp[r0 * 132 + col]     = ok0 ? c[nt][0] * SCALE + bh[r0 * 132 + col]     : -1e9f;
                scp[r0 * 132 + col + 1] = ok1 ? c[nt][1] * SCALE + bh[r0 * 132 + col + 1] : -1e9f;
                scp[r1 * 132 + col]     = ok0 ? c[nt][2] * SCALE + bh[r1 * 132 + col]     : -1e9f;
                scp[r1 * 132 + col + 1] = ok1 ? c[nt][3] * SCALE + bh[r1 * 132 + col + 1] : -1e9f;
            }
        }
        __syncthreads();

        // ---- softmax (fp32), write P as half ----
#pragma unroll
        for (int rr = 0; rr < 4; rr++) {
            int r = warp * 4 + rr;
            const float* row = scp + r * 132;
            float v0 = row[lane], v1 = row[lane + 32], v2 = row[lane + 64], v3 = row[lane + 96];
            float mx = fmaxf(fmaxf(v0, v1), fmaxf(v2, v3));
#pragma unroll
            for (int o2 = 16; o2; o2 >>= 1) mx = fmaxf(mx, __shfl_xor_sync(0xffffffffu, mx, o2));
            v0 = __expf(v0 - mx); v1 = __expf(v1 - mx);
            v2 = __expf(v2 - mx); v3 = __expf(v3 - mx);
            float sumv = v0 + v1 + v2 + v3;
#pragma unroll
            for (int o2 = 16; o2; o2 >>= 1) sumv += __shfl_xor_sync(0xffffffffu, sumv, o2);
            float invs = 1.0f / sumv;
            __half* pr = Ps + r * 136;
            pr[lane]      = __float2half(v0 * invs);
            pr[lane + 32] = __float2half(v1 * invs);
            pr[lane + 64] = __float2half(v2 * invs);
            pr[lane + 96] = __float2half(v3 * invs);
        }
        __syncthreads();

        // ---- PV: O = P @ V_h (32x32) ----
        {
            int m0 = (warp >> 2) * 16;
            int nd0 = (warp & 3) * 8;
            float o[4] = {0.0f, 0.0f, 0.0f, 0.0f};
#pragma unroll
            for (int kb = 0; kb < 8; kb++) {
                uint32_t af[4];
                ldsm_x4(af, psBase + (uint32_t)((m0 + lmA) * 136 + kb * 16 + lhA) * 2u);
                int l = lane & 15;
                uint32_t addr = vsBase + (uint32_t)((kb * 16 + l) * 136 + h * 32 + nd0) * 2u;
                uint32_t bf[2];
                asm volatile("ldmatrix.sync.aligned.m8n8.x2.trans.shared.b16 {%0,%1}, [%2];"
                             : "=r"(bf[0]), "=r"(bf[1]) : "r"(addr));
                MMA_F16(o, af, bf);
            }
            int r0 = m0 + gid;
            size_t t0 = ((size_t)b * N_ + nb * 32 + r0) * 128 + h * 32 + nd0 + 2 * qid;
            size_t t1 = t0 + (size_t)8 * 128;
            float2 g0 = __half22float2(*(const __half2*)(gh + t0));
            float2 g1 = __half22float2(*(const __half2*)(gh + t1));
            *(__half2*)(obh + t0) = __floats2half2_rn(g0.x * o[0], g0.y * o[1]);
            *(__half2*)(obh + t1) = __floats2half2_rn(g1.x * o[2], g1.y * o[3]);
        }
        __syncthreads();
    }
}

// ---------------------------------------------------------------------------
// Host launch
// ---------------------------------------------------------------------------
extern "C" void kernel_launch(void* const* d_in, const int* in_sizes, int n_in,
                              void* d_out, int out_size)
{
    const float* a       = (const float*)d_in[0];
    const float* s       = (const float*)d_in[1];
    const float* z       = (const float*)d_in[2];
    const float* apb_gam = (const float*)d_in[3];
    const float* apb_Wg  = (const float*)d_in[4];
    const float* apb_bg  = (const float*)d_in[5];
    const float* apb_Wsk = (const float*)d_in[6];
    const float* Wq      = (const float*)d_in[7];
    const float* bq      = (const float*)d_in[8];
    const float* Wk      = (const float*)d_in[9];
    const float* Wv      = (const float*)d_in[10];
    const float* Wgate   = (const float*)d_in[11];
    const float* Wo      = (const float*)d_in[12];
    const float* gamma_z = (const float*)d_in[13];
    const float* Wz      = (const float*)d_in[14];
    const float* Ws_last = (const float*)d_in[15];
    const float* bs_last = (const float*)d_in[16];
    const float* ct_gam  = (const float*)d_in[17];
    const float* ct_Wg   = (const float*)d_in[18];
    const float* ct_bg   = (const float*)d_in[19];
    const float* ct_Wsk  = (const float*)d_in[20];
    const float* Wa1     = (const float*)d_in[21];
    const float* Wa2     = (const float*)d_in[22];
    const float* Wb      = (const float*)d_in[23];
    const float* Ws      = (const float*)d_in[24];
    const float* bsv     = (const float*)d_in[25];
    float* out = (float*)d_out;

    float* S = nullptr;
    cudaGetSymbolAddress((void**)&S, g_scratch);
    float* a_n = S;
    float* ctp = S + SLOT;
    __half* HB = (__half*)(S + 2 * SLOT);
    auto hslot = [&](int k) { return HB + (size_t)k * SLOT; };
    __half* u1h    = hslot(0);   // M x 256
    __half* u2h    = hslot(2);   // M x 256
    __half* s_apbh = hslot(4);
    __half* s_cth  = hslot(5);
    __half* s_rh   = hslot(6);
    __half* a1h    = hslot(7);
    __half* a3h    = hslot(8);
    __half* obh    = hslot(9);
    __half* gapbh  = hslot(10);
    __half* kapbh  = hslot(11);
    __half* gcth   = hslot(12);
    __half* kcth   = hslot(13);
    __half* glasth = hslot(14);
    __half* sgh    = hslot(15);
    __half* qh     = hslot(16);
    __half* khb    = hslot(17);
    __half* vhb    = hslot(18);
    __half* ghb    = hslot(19);
    __half* wh     = hslot(20);  // weights

    __half* wWg   = wh + 0;
    __half* wWsk  = wh + 16384;
    __half* wcWg  = wh + 32768;
    __half* wcWsk = wh + 49152;
    __half* wWsl  = wh + 65536;
    __half* wWs   = wh + 81920;
    __half* wWq   = wh + 98304;
    __half* wWk   = wh + 114688;
    __half* wWv   = wh + 131072;
    __half* wWgt  = wh + 147456;
    __half* wWo   = wh + 163840;
    __half* wWa1  = wh + 180224;  // [256][128]
    __half* wWa2  = wh + 212992;
    __half* wWb   = wh + 245760;  // [128][256]

    WtPack wp;
    const float* wsrc[14] = {apb_Wg, apb_Wsk, ct_Wg, ct_Wsk, Ws_last, Ws, Wq, Wk, Wv,
                             Wgate, Wo, Wa1, Wa2, Wb};
    __half* wdst[14] = {wWg, wWsk, wcWg, wcWsk, wWsl, wWs, wWq, wWk, wWv,
                        wWgt, wWo, wWa1, wWa2, wWb};
    int wK[14] = {128,128,128,128,128,128,128,128,128,128,128,128,128,256};
    int wN[14] = {128,128,128,128,128,128,128,128,128,128,128,256,256,128};
    for (int i = 0; i < 14; i++) { wp.src[i] = wsrc[i]; wp.dst[i] = wdst[i];
                                   wp.K[i] = wK[i]; wp.N[i] = wN[i]; }
    cvtw_kernel<<<dim3(16, 14), 256>>>(wp);

    ln_kernel<<<M_ / 8, 256>>>(a, s, apb_gam, ct_gam, a_n, s_apbh, s_cth, s_rh);

    cudaFuncSetAttribute(gemm_h, cudaFuncAttributeMaxDynamicSharedMemorySize, GEMM_SMEM);
    cudaFuncSetAttribute(attn_kernel, cudaFuncAttributeMaxDynamicSharedMemorySize,
                         ATTN_SMEM_BYTES);

    auto mkseg = [&](const __half* A, const __half* Wt, const float* bias, void* C,
                     int ep, const __half* e1h, const float* e2, int ldC, int outh) {
        Seg sgm; sgm.A = A; sgm.Wt = Wt; sgm.bias = bias; sgm.C = C;
        sgm.e1h = e1h; sgm.e2 = e2; sgm.ldC = ldC; sgm.ep = ep; sgm.outh = outh;
        return sgm;
    };

    // G1: 6 segments from s-derived activations
    {
        GemmArgs g{};
        g.seg[0] = mkseg(s_apbh, wWg,   apb_bg,  gapbh,  1, nullptr, nullptr, 128, 1);
        g.seg[1] = mkseg(s_apbh, wWsk,  nullptr, kapbh,  0, nullptr, nullptr, 128, 1);
        g.seg[2] = mkseg(s_cth,  wcWg,  ct_bg,   gcth,   1, nullptr, nullptr, 128, 1);
        g.seg[3] = mkseg(s_cth,  wcWsk, nullptr, kcth,   0, nullptr, nullptr, 128, 1);
        g.seg[4] = mkseg(s_rh,   wWsl,  bs_last, glasth, 1, nullptr, nullptr, 128, 1);
        g.seg[5] = mkseg(s_rh,   wWs,   bsv,     sgh,    1, nullptr, nullptr, 128, 1);
        gemm_h<<<dim3(M_ / 128, 6), 256, GEMM_SMEM>>>(128, 0, nullptr, nullptr, g);
    }

    combine1_kernel<<<(int)(SLOT / 4 / 256), 256>>>(gapbh, kapbh, gcth, kcth, a_n, a1h, a3h);

    // G2: qkv/gate from a1h; u1/u2 from a3h
    {
        GemmArgs g{};
        g.seg[0] = mkseg(a1h, wWq,          bq,      qh,        0, nullptr, nullptr, 128, 1);
        g.seg[1] = mkseg(a1h, wWk,          nullptr, khb,       0, nullptr, nullptr, 128, 1);
        g.seg[2] = mkseg(a1h, wWv,          nullptr, vhb,       0, nullptr, nullptr, 128, 1);
        g.seg[3] = mkseg(a1h, wWgt,         nullptr, ghb,       1, nullptr, nullptr, 128, 1);
        g.seg[4] = mkseg(a3h, wWa1,         nullptr, u1h,       0, nullptr, nullptr, 256, 1);
        g.seg[5] = mkseg(a3h, wWa1 + 16384, nullptr, u1h + 128, 0, nullptr, nullptr, 256, 1);
        g.seg[6] = mkseg(a3h, wWa2,         nullptr, u2h,       0, nullptr, nullptr, 256, 1);
        g.seg[7] = mkseg(a3h, wWa2 + 16384, nullptr, u2h + 128, 0, nullptr, nullptr, 256, 1);
        gemm_h<<<dim3(M_ / 128, 8), 256, GEMM_SMEM>>>(128, 0, nullptr, nullptr, g);
    }

    // G3: ct_out = sgh * (silu(u1)*u2 @ Wb), K=256
    {
        GemmArgs g{};
        g.seg[0] = mkseg(nullptr, wWb, nullptr, ctp, 2, sgh, nullptr, 128, 0);
        gemm_h<<<dim3(M_ / 128, 1), 256, GEMM_SMEM>>>(256, 1, u1h, u2h, g);
    }

    // attention
    attn_kernel<<<dim3(NB_, B_), 256, ATTN_SMEM_BYTES>>>(
        qh, khb, vhb, z, gamma_z, Wz, ghb, obh);

    // G4: out = glasth * (obh @ Wo) + ctp
    {
        GemmArgs g{};
        g.seg[0] = mkseg(obh, wWo, nullptr, out, 3, glasth, ctp, 128, 0);
        gemm_h<<<dim3(M_ / 128, 1), 256, GEMM_SMEM>>>(128, 0, nullptr, nullptr, g);
    }
}